// round 1
// baseline (speedup 1.0000x reference)
#include <cuda_runtime.h>
#include <math.h>
#include <stddef.h>

#define B_  2
#define N_  4096
#define C_  1024
#define H_  16
#define D_  64
#define BH_ (B_*H_)

// ---------------- scratch (device globals; no allocs allowed) ----------------
__device__ float g_qkv[(size_t)B_*N_*3*C_];   // [B,N,3C]
__device__ float g_q  [(size_t)BH_*N_*D_];    // [B,H,N,D] (LN'd, pre-scaled)
__device__ float g_k  [(size_t)BH_*N_*D_];    // [B,H,N,D] (LN'd)
__device__ float g_v  [(size_t)BH_*N_*D_];    // [B,H,N,D]
__device__ float g_ao [(size_t)B_*N_*C_];     // [B,N,C] attention output

// =============================================================================
// Generic fp32 GEMM: C[M,Nout] = A[M,K] @ W[Nout,K]^T + bias
// 128x128 block tile, BK=16, 256 threads, 8x8 micro-tile.
// =============================================================================
__global__ __launch_bounds__(256) void sgemm_bias(
    const float* __restrict__ A, const float* __restrict__ W,
    const float* __restrict__ bias, float* __restrict__ Cmat,
    int M, int Nout, int K)
{
    __shared__ float As[16][132];   // [k][m], padded
    __shared__ float Ws[16][132];   // [k][n], padded

    const int tid  = threadIdx.x;
    const int bm   = blockIdx.y * 128;
    const int bn   = blockIdx.x * 128;
    const int lrow = tid >> 2;          // 0..63
    const int lcol = (tid & 3) * 4;     // 0,4,8,12
    const int tx   = tid & 15;
    const int ty   = tid >> 4;

    const float* Ap = A + (size_t)(bm + lrow) * K + lcol;
    const float* Wp = W + (size_t)(bn + lrow) * K + lcol;

    float acc[8][8];
    #pragma unroll
    for (int i = 0; i < 8; i++)
        #pragma unroll
        for (int j = 0; j < 8; j++) acc[i][j] = 0.f;

    for (int k0 = 0; k0 < K; k0 += 16) {
        #pragma unroll
        for (int s = 0; s < 2; s++) {
            const int r = lrow + s * 64;
            float4 va = *(const float4*)(Ap + (size_t)s * 64 * K + k0);
            As[lcol+0][r] = va.x; As[lcol+1][r] = va.y;
            As[lcol+2][r] = va.z; As[lcol+3][r] = va.w;
            float4 vw = *(const float4*)(Wp + (size_t)s * 64 * K + k0);
            Ws[lcol+0][r] = vw.x; Ws[lcol+1][r] = vw.y;
            Ws[lcol+2][r] = vw.z; Ws[lcol+3][r] = vw.w;
        }
        __syncthreads();

        #pragma unroll
        for (int kk = 0; kk < 16; kk++) {
            float a[8], b[8];
            float4 t0 = *(const float4*)&As[kk][ty*4];
            float4 t1 = *(const float4*)&As[kk][64 + ty*4];
            a[0]=t0.x; a[1]=t0.y; a[2]=t0.z; a[3]=t0.w;
            a[4]=t1.x; a[5]=t1.y; a[6]=t1.z; a[7]=t1.w;
            float4 u0 = *(const float4*)&Ws[kk][tx*4];
            float4 u1 = *(const float4*)&Ws[kk][64 + tx*4];
            b[0]=u0.x; b[1]=u0.y; b[2]=u0.z; b[3]=u0.w;
            b[4]=u1.x; b[5]=u1.y; b[6]=u1.z; b[7]=u1.w;
            #pragma unroll
            for (int i = 0; i < 8; i++)
                #pragma unroll
                for (int j = 0; j < 8; j++)
                    acc[i][j] += a[i] * b[j];
        }
        __syncthreads();
    }

    float bv[8];
    #pragma unroll
    for (int j = 0; j < 4; j++) {
        bv[j]   = bias[bn + tx*4 + j];
        bv[4+j] = bias[bn + 64 + tx*4 + j];
    }
    #pragma unroll
    for (int i = 0; i < 8; i++) {
        int row = bm + ((i < 4) ? (ty*4 + i) : (64 + ty*4 + (i-4)));
        float* cp = Cmat + (size_t)row * Nout + bn;
        *(float4*)(cp + tx*4) =
            make_float4(acc[i][0]+bv[0], acc[i][1]+bv[1], acc[i][2]+bv[2], acc[i][3]+bv[3]);
        *(float4*)(cp + 64 + tx*4) =
            make_float4(acc[i][4]+bv[4], acc[i][5]+bv[5], acc[i][6]+bv[6], acc[i][7]+bv[7]);
    }
}

// =============================================================================
// LayerNorm over D=64 per (b,h,n) for q and k + v copy; splits [B,N,3C] into
// [B,H,N,D] q (scaled by D^-0.5), k, v. One warp per (b,h,n).
// =============================================================================
__global__ __launch_bounds__(256) void ln_split(
    const float* __restrict__ qkv,
    const float* __restrict__ qw, const float* __restrict__ qb,
    const float* __restrict__ kw, const float* __restrict__ kb,
    float* __restrict__ Qo, float* __restrict__ Ko, float* __restrict__ Vo)
{
    const int gw   = (blockIdx.x * blockDim.x + threadIdx.x) >> 5;  // 0..B*H*N-1
    const int lane = threadIdx.x & 31;
    const int n = gw & (N_ - 1);
    const int h = (gw >> 12) & (H_ - 1);
    const int b = gw >> 16;

    const float* base = qkv + ((size_t)(b * N_ + n)) * (3 * C_) + h * D_;
    const size_t oidx = ((size_t)((b * H_ + h) * N_) + n) * D_ + lane * 2;
    const int d = lane * 2;

    // v copy
    float2 vv = *(const float2*)(base + 2 * C_ + d);
    *(float2*)(Vo + oidx) = vv;

    const float inv64 = 1.f / 64.f;
    // ---- q ----
    {
        float2 qv = *(const float2*)(base + d);
        float s = qv.x + qv.y, ss = qv.x*qv.x + qv.y*qv.y;
        #pragma unroll
        for (int m = 16; m; m >>= 1) {
            s  += __shfl_xor_sync(0xffffffffu, s,  m);
            ss += __shfl_xor_sync(0xffffffffu, ss, m);
        }
        float mu = s * inv64;
        float var = fmaxf(ss * inv64 - mu * mu, 0.f);
        float rstd = rsqrtf(var + 1e-5f);
        const float sc = 0.125f;  // D^-0.5
        float2 r;
        r.x = ((qv.x - mu) * rstd * qw[d]     + qb[d])     * sc;
        r.y = ((qv.y - mu) * rstd * qw[d + 1] + qb[d + 1]) * sc;
        *(float2*)(Qo + oidx) = r;
    }
    // ---- k ----
    {
        float2 kv = *(const float2*)(base + C_ + d);
        float s = kv.x + kv.y, ss = kv.x*kv.x + kv.y*kv.y;
        #pragma unroll
        for (int m = 16; m; m >>= 1) {
            s  += __shfl_xor_sync(0xffffffffu, s,  m);
            ss += __shfl_xor_sync(0xffffffffu, ss, m);
        }
        float mu = s * inv64;
        float var = fmaxf(ss * inv64 - mu * mu, 0.f);
        float rstd = rsqrtf(var + 1e-5f);
        float2 r;
        r.x = (kv.x - mu) * rstd * kw[d]     + kb[d];
        r.y = (kv.y - mu) * rstd * kw[d + 1] + kb[d + 1];
        *(float2*)(Ko + oidx) = r;
    }
}

// =============================================================================
// Flash attention (fp32): per block, 64 query rows for one (b,h).
// 256 threads; each owns a 4x4 S/O micro-tile. Online softmax in registers
// (half-warp shuffles). Output written directly in [B,N,C] layout.
// =============================================================================
#define SS 68   // padded row stride (floats); 68*4 bytes = 16B-aligned

__global__ __launch_bounds__(256) void attn_fwd(
    const float* __restrict__ Q, const float* __restrict__ Kg,
    const float* __restrict__ Vg, float* __restrict__ AO)
{
    extern __shared__ float sm[];
    float* Qs = sm;              // [64 k][64 r] transposed, stride SS
    float* Ks = Qs + 64 * SS;    // [64 k][64 c] transposed, stride SS
    float* Vs = Ks + 64 * SS;    // [64 j][64 c], stride SS
    float* Ss = Vs + 64 * SS;    // [64 r][64 j] (P tile), stride SS

    const int tid = threadIdx.x;
    const int bh  = blockIdx.y;
    const int q0  = blockIdx.x * 64;

    const float* Qb = Q  + ((size_t)bh * N_ + q0) * D_;
    const float* Kb = Kg + (size_t)bh * N_ * D_;
    const float* Vb = Vg + (size_t)bh * N_ * D_;

    const int lr = tid >> 2;          // 0..63 (load row)
    const int t4 = tid & 3;
    const int r0 = (tid >> 4) * 4;    // compute rows
    const int c0 = (tid & 15) * 4;    // compute cols

    // load Q transposed: Qs[k][r]
    #pragma unroll
    for (int i = 0; i < 4; i++) {
        const int kcol = t4 * 4 + i * 16;
        float4 v = *(const float4*)(Qb + (size_t)lr * D_ + kcol);
        Qs[(kcol+0)*SS + lr] = v.x; Qs[(kcol+1)*SS + lr] = v.y;
        Qs[(kcol+2)*SS + lr] = v.z; Qs[(kcol+3)*SS + lr] = v.w;
    }

    float o[16];
    #pragma unroll
    for (int i = 0; i < 16; i++) o[i] = 0.f;
    float mstat[4], lstat[4];
    #pragma unroll
    for (int i = 0; i < 4; i++) { mstat[i] = -1e30f; lstat[i] = 0.f; }

    for (int t = 0; t < N_ / 64; t++) {
        __syncthreads();   // prev iter done with Ks/Vs/Ss; Q stores visible at t=0
        // load K (transposed) and V tiles
        {
            const float* kp = Kb + (size_t)(t * 64 + lr) * D_;
            const float* vp = Vb + (size_t)(t * 64 + lr) * D_;
            #pragma unroll
            for (int i = 0; i < 4; i++) {
                const int kcol = t4 * 4 + i * 16;
                float4 kv = *(const float4*)(kp + kcol);
                Ks[(kcol+0)*SS + lr] = kv.x; Ks[(kcol+1)*SS + lr] = kv.y;
                Ks[(kcol+2)*SS + lr] = kv.z; Ks[(kcol+3)*SS + lr] = kv.w;
                *(float4*)(Vs + (size_t)lr * SS + kcol) = *(const float4*)(vp + kcol);
            }
        }
        __syncthreads();

        // S = Q @ K^T  (4x4 per thread)
        float s[4][4];
        #pragma unroll
        for (int i = 0; i < 4; i++)
            #pragma unroll
            for (int j = 0; j < 4; j++) s[i][j] = 0.f;
        #pragma unroll 8
        for (int kk = 0; kk < 64; kk++) {
            float4 qa = *(const float4*)(Qs + kk * SS + r0);
            float4 kb = *(const float4*)(Ks + kk * SS + c0);
            s[0][0] += qa.x*kb.x; s[0][1] += qa.x*kb.y; s[0][2] += qa.x*kb.z; s[0][3] += qa.x*kb.w;
            s[1][0] += qa.y*kb.x; s[1][1] += qa.y*kb.y; s[1][2] += qa.y*kb.z; s[1][3] += qa.y*kb.w;
            s[2][0] += qa.z*kb.x; s[2][1] += qa.z*kb.y; s[2][2] += qa.z*kb.z; s[2][3] += qa.z*kb.w;
            s[3][0] += qa.w*kb.x; s[3][1] += qa.w*kb.y; s[3][2] += qa.w*kb.z; s[3][3] += qa.w*kb.w;
        }

        // online softmax per row (reduce across the 16 lanes of the half-warp
        // that share this row group; lanes tid%16 == tx all have same r0)
        #pragma unroll
        for (int i = 0; i < 4; i++) {
            float mx = fmaxf(fmaxf(s[i][0], s[i][1]), fmaxf(s[i][2], s[i][3]));
            mx = fmaxf(mx, __shfl_xor_sync(0xffffffffu, mx, 1));
            mx = fmaxf(mx, __shfl_xor_sync(0xffffffffu, mx, 2));
            mx = fmaxf(mx, __shfl_xor_sync(0xffffffffu, mx, 4));
            mx = fmaxf(mx, __shfl_xor_sync(0xffffffffu, mx, 8));
            float m_new = fmaxf(mstat[i], mx);
            float corr  = __expf(mstat[i] - m_new);
            mstat[i] = m_new;
            float ls = 0.f;
            #pragma unroll
            for (int j = 0; j < 4; j++) {
                s[i][j] = __expf(s[i][j] - m_new);
                ls += s[i][j];
            }
            ls += __shfl_xor_sync(0xffffffffu, ls, 1);
            ls += __shfl_xor_sync(0xffffffffu, ls, 2);
            ls += __shfl_xor_sync(0xffffffffu, ls, 4);
            ls += __shfl_xor_sync(0xffffffffu, ls, 8);
            lstat[i] = lstat[i] * corr + ls;
            o[i*4+0] *= corr; o[i*4+1] *= corr; o[i*4+2] *= corr; o[i*4+3] *= corr;
            *(float4*)(Ss + (size_t)(r0 + i) * SS + c0) =
                make_float4(s[i][0], s[i][1], s[i][2], s[i][3]);
        }
        __syncthreads();

        // O += P @ V
        #pragma unroll 4
        for (int j4 = 0; j4 < 64; j4 += 4) {
            float4 p[4];
            #pragma unroll
            for (int i = 0; i < 4; i++)
                p[i] = *(const float4*)(Ss + (size_t)(r0 + i) * SS + j4);
            #pragma unroll
            for (int jj = 0; jj < 4; jj++) {
                float4 vv = *(const float4*)(Vs + (size_t)(j4 + jj) * SS + c0);
                #pragma unroll
                for (int i = 0; i < 4; i++) {
                    float pv = (jj == 0) ? p[i].x : (jj == 1) ? p[i].y
                             : (jj == 2) ? p[i].z : p[i].w;
                    o[i*4+0] += pv * vv.x; o[i*4+1] += pv * vv.y;
                    o[i*4+2] += pv * vv.z; o[i*4+3] += pv * vv.w;
                }
            }
        }
    }

    // epilogue: normalize and write [B,N,C] (n = q0+row, c = h*64 + col)
    const int b = bh >> 4, h = bh & 15;
    float* op = AO + ((size_t)(b * N_ + q0) * C_) + h * D_;
    #pragma unroll
    for (int i = 0; i < 4; i++) {
        float inv = 1.f / lstat[i];
        *(float4*)(op + (size_t)(r0 + i) * C_ + c0) =
            make_float4(o[i*4+0]*inv, o[i*4+1]*inv, o[i*4+2]*inv, o[i*4+3]*inv);
    }
}

// =============================================================================
extern "C" void kernel_launch(void* const* d_in, const int* in_sizes, int n_in,
                              void* d_out, int out_size)
{
    const float* x      = (const float*)d_in[0];
    const float* qkv_w  = (const float*)d_in[1];
    const float* qkv_b  = (const float*)d_in[2];
    const float* qnw    = (const float*)d_in[3];
    const float* qnb    = (const float*)d_in[4];
    const float* knw    = (const float*)d_in[5];
    const float* knb    = (const float*)d_in[6];
    const float* proj_w = (const float*)d_in[7];
    const float* proj_b = (const float*)d_in[8];
    float* out = (float*)d_out;

    float *qkv, *q, *k, *v, *ao;
    cudaGetSymbolAddress((void**)&qkv, g_qkv);
    cudaGetSymbolAddress((void**)&q,   g_q);
    cudaGetSymbolAddress((void**)&k,   g_k);
    cudaGetSymbolAddress((void**)&v,   g_v);
    cudaGetSymbolAddress((void**)&ao,  g_ao);

    // 1) QKV projection: [8192,1024] @ [3072,1024]^T
    {
        dim3 grid(3 * C_ / 128, (B_ * N_) / 128);
        sgemm_bias<<<grid, 256>>>(x, qkv_w, qkv_b, qkv, B_ * N_, 3 * C_, C_);
    }
    // 2) per-head LN + split
    {
        int warps = B_ * H_ * N_;
        ln_split<<<warps / 8, 256>>>(qkv, qnw, qnb, knw, knb, q, k, v);
    }
    // 3) attention
    {
        const int smem = 4 * 64 * SS * (int)sizeof(float);  // 69632 B
        cudaFuncSetAttribute(attn_fwd, cudaFuncAttributeMaxDynamicSharedMemorySize, smem);
        dim3 grid(N_ / 64, BH_);
        attn_fwd<<<grid, 256, smem>>>(q, k, v, ao);
    }
    // 4) output projection: [8192,1024] @ [1024,1024]^T -> d_out
    {
        dim3 grid(C_ / 128, (B_ * N_) / 128);
        sgemm_bias<<<grid, 256>>>(ao, proj_w, proj_b, out, B_ * N_, C_, C_);
    }
}

// round 2
// speedup vs baseline: 2.7771x; 2.7771x over previous
#include <cuda_runtime.h>
#include <math.h>
#include <stdint.h>
#include <stddef.h>

#define B_  2
#define N_  4096
#define C_  1024
#define H_  16
#define D_  64
#define BH_ (B_*H_)

// ---------------- scratch (device globals; no allocs allowed) ----------------
__device__ float g_qkv[(size_t)B_*N_*3*C_];   // [B,N,3C]
__device__ float g_q  [(size_t)BH_*N_*D_];    // [B,H,N,D] (LN'd, pre-scaled)
__device__ float g_k  [(size_t)BH_*N_*D_];    // [B,H,N,D] (LN'd)
__device__ float g_v  [(size_t)BH_*N_*D_];    // [B,H,N,D]
__device__ float g_ao [(size_t)B_*N_*C_];     // [B,N,C] attention output

// ---------------- tf32 helpers ----------------
__device__ __forceinline__ float f2tf(float x) {
    uint32_t u;
    asm("cvt.rna.tf32.f32 %0, %1;" : "=r"(u) : "f"(x));
    return __uint_as_float(u);
}

__device__ __forceinline__ void mma8(float* c, const uint32_t* a, const uint32_t* b) {
    asm volatile(
        "mma.sync.aligned.m16n8k8.row.col.f32.tf32.tf32.f32 "
        "{%0,%1,%2,%3}, {%4,%5,%6,%7}, {%8,%9}, {%0,%1,%2,%3};"
        : "+f"(c[0]), "+f"(c[1]), "+f"(c[2]), "+f"(c[3])
        : "r"(a[0]), "r"(a[1]), "r"(a[2]), "r"(a[3]), "r"(b[0]), "r"(b[1]));
}

// =============================================================================
// TF32 tensor-core GEMM: C[M,Nout] = A[M,K] @ W[Nout,K]^T + bias
// 128x128 block tile, BK=32, 256 threads (8 warps, 2x4), warp tile 64x32.
// =============================================================================
#define GSTR 36  // smem row stride; 36 % 32 == 4 -> conflict-free frag loads

__global__ __launch_bounds__(256) void gemm_tf32(
    const float* __restrict__ A, const float* __restrict__ W,
    const float* __restrict__ bias, float* __restrict__ Cmat,
    int M, int Nout, int K)
{
    __shared__ float As[128][GSTR];
    __shared__ float Bs[128][GSTR];

    const int tid  = threadIdx.x;
    const int warp = tid >> 5, lane = tid & 31;
    const int mw   = warp >> 2, nw = warp & 3;      // 2 x 4 warp grid
    const int g    = lane >> 2, tg = lane & 3;
    const int bm   = blockIdx.y * 128, bn = blockIdx.x * 128;

    float acc[4][4][4];
    #pragma unroll
    for (int i = 0; i < 4; i++)
        #pragma unroll
        for (int j = 0; j < 4; j++)
            #pragma unroll
            for (int e = 0; e < 4; e++) acc[i][j][e] = 0.f;

    for (int k0 = 0; k0 < K; k0 += 32) {
        // load 128x32 A and B tiles (4 float4 per thread each), convert to tf32
        #pragma unroll
        for (int j = 0; j < 4; j++) {
            const int f4  = tid + 256 * j;
            const int row = f4 >> 3;
            const int cc  = (f4 & 7) * 4;
            float4 va = *(const float4*)(A + (size_t)(bm + row) * K + k0 + cc);
            As[row][cc+0] = f2tf(va.x); As[row][cc+1] = f2tf(va.y);
            As[row][cc+2] = f2tf(va.z); As[row][cc+3] = f2tf(va.w);
            float4 vb = *(const float4*)(W + (size_t)(bn + row) * K + k0 + cc);
            Bs[row][cc+0] = f2tf(vb.x); Bs[row][cc+1] = f2tf(vb.y);
            Bs[row][cc+2] = f2tf(vb.z); Bs[row][cc+3] = f2tf(vb.w);
        }
        __syncthreads();

        #pragma unroll
        for (int ks = 0; ks < 4; ks++) {
            const int kk = ks * 8;
            uint32_t af[4][4];
            #pragma unroll
            for (int mt = 0; mt < 4; mt++) {
                const int rb = mw * 64 + mt * 16;
                af[mt][0] = __float_as_uint(As[rb + g    ][kk + tg    ]);
                af[mt][1] = __float_as_uint(As[rb + 8 + g][kk + tg    ]);
                af[mt][2] = __float_as_uint(As[rb + g    ][kk + 4 + tg]);
                af[mt][3] = __float_as_uint(As[rb + 8 + g][kk + 4 + tg]);
            }
            uint32_t bf[4][2];
            #pragma unroll
            for (int nt = 0; nt < 4; nt++) {
                const int nb = nw * 32 + nt * 8;
                bf[nt][0] = __float_as_uint(Bs[nb + g][kk + tg    ]);
                bf[nt][1] = __float_as_uint(Bs[nb + g][kk + 4 + tg]);
            }
            #pragma unroll
            for (int mt = 0; mt < 4; mt++)
                #pragma unroll
                for (int nt = 0; nt < 4; nt++)
                    mma8(acc[mt][nt], af[mt], bf[nt]);
        }
        __syncthreads();
    }

    // epilogue: add bias, write float2 pairs
    #pragma unroll
    for (int mt = 0; mt < 4; mt++) {
        const int row0 = bm + mw * 64 + mt * 16 + g;
        #pragma unroll
        for (int nt = 0; nt < 4; nt++) {
            const int col = bn + nw * 32 + nt * 8 + tg * 2;
            const float b0 = bias[col], b1 = bias[col + 1];
            *(float2*)(Cmat + (size_t)row0 * Nout + col) =
                make_float2(acc[mt][nt][0] + b0, acc[mt][nt][1] + b1);
            *(float2*)(Cmat + (size_t)(row0 + 8) * Nout + col) =
                make_float2(acc[mt][nt][2] + b0, acc[mt][nt][3] + b1);
        }
    }
}

// =============================================================================
// LayerNorm over D=64 per (b,h,n) for q and k + v copy (unchanged from R1).
// =============================================================================
__global__ __launch_bounds__(256) void ln_split(
    const float* __restrict__ qkv,
    const float* __restrict__ qw, const float* __restrict__ qb,
    const float* __restrict__ kw, const float* __restrict__ kb,
    float* __restrict__ Qo, float* __restrict__ Ko, float* __restrict__ Vo)
{
    const int gw   = (blockIdx.x * blockDim.x + threadIdx.x) >> 5;
    const int lane = threadIdx.x & 31;
    const int n = gw & (N_ - 1);
    const int h = (gw >> 12) & (H_ - 1);
    const int b = gw >> 16;

    const float* base = qkv + ((size_t)(b * N_ + n)) * (3 * C_) + h * D_;
    const size_t oidx = ((size_t)((b * H_ + h) * N_) + n) * D_ + lane * 2;
    const int d = lane * 2;

    float2 vv = *(const float2*)(base + 2 * C_ + d);
    *(float2*)(Vo + oidx) = vv;

    const float inv64 = 1.f / 64.f;
    {
        float2 qv = *(const float2*)(base + d);
        float s = qv.x + qv.y, ss = qv.x*qv.x + qv.y*qv.y;
        #pragma unroll
        for (int m = 16; m; m >>= 1) {
            s  += __shfl_xor_sync(0xffffffffu, s,  m);
            ss += __shfl_xor_sync(0xffffffffu, ss, m);
        }
        float mu = s * inv64;
        float var = fmaxf(ss * inv64 - mu * mu, 0.f);
        float rstd = rsqrtf(var + 1e-5f);
        const float sc = 0.125f;  // D^-0.5
        float2 r;
        r.x = ((qv.x - mu) * rstd * qw[d]     + qb[d])     * sc;
        r.y = ((qv.y - mu) * rstd * qw[d + 1] + qb[d + 1]) * sc;
        *(float2*)(Qo + oidx) = r;
    }
    {
        float2 kv = *(const float2*)(base + C_ + d);
        float s = kv.x + kv.y, ss = kv.x*kv.x + kv.y*kv.y;
        #pragma unroll
        for (int m = 16; m; m >>= 1) {
            s  += __shfl_xor_sync(0xffffffffu, s,  m);
            ss += __shfl_xor_sync(0xffffffffu, ss, m);
        }
        float mu = s * inv64;
        float var = fmaxf(ss * inv64 - mu * mu, 0.f);
        float rstd = rsqrtf(var + 1e-5f);
        float2 r;
        r.x = (kv.x - mu) * rstd * kw[d]     + kb[d];
        r.y = (kv.y - mu) * rstd * kw[d + 1] + kb[d + 1];
        *(float2*)(Ko + oidx) = r;
    }
}

// =============================================================================
// Flash attention, TF32 tensor cores. Block = 128 q-rows of one (b,h).
// 8 warps; warp owns 16 rows. Bc=64 key tile. P routed through smem.
// =============================================================================
#define AST 68  // smem row stride; 68 % 32 == 4 -> conflict-free frag loads

__global__ __launch_bounds__(256) void attn_tf32(
    const float* __restrict__ Q, const float* __restrict__ Kg,
    const float* __restrict__ Vg, float* __restrict__ AO)
{
    extern __shared__ float sm[];
    float* Qs = sm;                 // [128][AST]  q rows (tf32)
    float* Ks = Qs + 128 * AST;     // [64][AST]   key rows (tf32)
    float* Vt = Ks + 64 * AST;      // [64][AST]   V^T: [d][key] (tf32)
    float* Ps = Vt + 64 * AST;      // [128][AST]  P tile (tf32)

    const int tid  = threadIdx.x;
    const int warp = tid >> 5, lane = tid & 31;
    const int g    = lane >> 2, tg = lane & 3;
    const int bh   = blockIdx.y;
    const int q0   = blockIdx.x * 128;
    const int mrow = warp * 16;

    const float* Qb = Q  + ((size_t)bh * N_ + q0) * D_;
    const float* Kb = Kg + (size_t)bh * N_ * D_;
    const float* Vb = Vg + (size_t)bh * N_ * D_;

    // load Q tile (128x64), tf32-converted
    #pragma unroll
    for (int j = 0; j < 8; j++) {
        const int f4  = tid + 256 * j;
        const int row = f4 >> 4;
        const int cc  = (f4 & 15) * 4;
        float4 v = *(const float4*)(Qb + (size_t)row * D_ + cc);
        Qs[row * AST + cc + 0] = f2tf(v.x); Qs[row * AST + cc + 1] = f2tf(v.y);
        Qs[row * AST + cc + 2] = f2tf(v.z); Qs[row * AST + cc + 3] = f2tf(v.w);
    }

    float o[8][4];
    #pragma unroll
    for (int nt = 0; nt < 8; nt++)
        #pragma unroll
        for (int e = 0; e < 4; e++) o[nt][e] = 0.f;
    float ms[2] = { -1e30f, -1e30f };
    float ls[2] = { 0.f, 0.f };

    for (int t = 0; t < N_ / 64; t++) {
        __syncthreads();   // prev iter done with Ks/Vt (and Q stores visible at t=0)
        // load K (natural) + V (transposed) tiles, tf32-converted
        #pragma unroll
        for (int j = 0; j < 4; j++) {
            const int f4  = tid + 256 * j;
            const int row = f4 >> 4;
            const int cc  = (f4 & 15) * 4;
            float4 kv = *(const float4*)(Kb + (size_t)(t * 64 + row) * D_ + cc);
            Ks[row * AST + cc + 0] = f2tf(kv.x); Ks[row * AST + cc + 1] = f2tf(kv.y);
            Ks[row * AST + cc + 2] = f2tf(kv.z); Ks[row * AST + cc + 3] = f2tf(kv.w);
            float4 vv = *(const float4*)(Vb + (size_t)(t * 64 + row) * D_ + cc);
            Vt[(cc + 0) * AST + row] = f2tf(vv.x);
            Vt[(cc + 1) * AST + row] = f2tf(vv.y);
            Vt[(cc + 2) * AST + row] = f2tf(vv.z);
            Vt[(cc + 3) * AST + row] = f2tf(vv.w);
        }
        __syncthreads();

        // ---- S = Q @ K^T : warp computes 16x64 ----
        float sacc[8][4];
        #pragma unroll
        for (int nt = 0; nt < 8; nt++)
            #pragma unroll
            for (int e = 0; e < 4; e++) sacc[nt][e] = 0.f;

        #pragma unroll
        for (int ks = 0; ks < 8; ks++) {
            const int kk = ks * 8;
            uint32_t af[4];
            af[0] = __float_as_uint(Qs[(mrow + g    ) * AST + kk + tg    ]);
            af[1] = __float_as_uint(Qs[(mrow + 8 + g) * AST + kk + tg    ]);
            af[2] = __float_as_uint(Qs[(mrow + g    ) * AST + kk + 4 + tg]);
            af[3] = __float_as_uint(Qs[(mrow + 8 + g) * AST + kk + 4 + tg]);
            #pragma unroll
            for (int nt = 0; nt < 8; nt++) {
                const int nb = nt * 8;
                uint32_t bf[2];
                bf[0] = __float_as_uint(Ks[(nb + g) * AST + kk + tg    ]);
                bf[1] = __float_as_uint(Ks[(nb + g) * AST + kk + 4 + tg]);
                mma8(sacc[nt], af, bf);
            }
        }

        // ---- online softmax (rows mrow+g and mrow+8+g) ----
        #pragma unroll
        for (int hh = 0; hh < 2; hh++) {
            float mx = -1e30f;
            #pragma unroll
            for (int nt = 0; nt < 8; nt++)
                mx = fmaxf(mx, fmaxf(sacc[nt][2*hh], sacc[nt][2*hh+1]));
            mx = fmaxf(mx, __shfl_xor_sync(0xffffffffu, mx, 1));
            mx = fmaxf(mx, __shfl_xor_sync(0xffffffffu, mx, 2));
            const float mn   = fmaxf(ms[hh], mx);
            const float corr = __expf(ms[hh] - mn);
            ms[hh] = mn;
            float sum = 0.f;
            #pragma unroll
            for (int nt = 0; nt < 8; nt++) {
                float p0 = __expf(sacc[nt][2*hh]     - mn);
                float p1 = __expf(sacc[nt][2*hh + 1] - mn);
                sacc[nt][2*hh] = p0; sacc[nt][2*hh+1] = p1;
                sum += p0 + p1;
            }
            sum += __shfl_xor_sync(0xffffffffu, sum, 1);
            sum += __shfl_xor_sync(0xffffffffu, sum, 2);
            ls[hh] = ls[hh] * corr + sum;
            #pragma unroll
            for (int nt = 0; nt < 8; nt++) {
                o[nt][2*hh]   *= corr;
                o[nt][2*hh+1] *= corr;
            }
        }

        // ---- store P to smem (warp-private rows) ----
        #pragma unroll
        for (int nt = 0; nt < 8; nt++) {
            const int col = nt * 8 + tg * 2;
            *(float2*)(Ps + (size_t)(mrow + g) * AST + col) =
                make_float2(f2tf(sacc[nt][0]), f2tf(sacc[nt][1]));
            *(float2*)(Ps + (size_t)(mrow + 8 + g) * AST + col) =
                make_float2(f2tf(sacc[nt][2]), f2tf(sacc[nt][3]));
        }
        __syncwarp();   // warp reads only its own P rows

        // ---- O += P @ V ----
        #pragma unroll
        for (int ks = 0; ks < 8; ks++) {
            const int kk = ks * 8;
            uint32_t af[4];
            af[0] = __float_as_uint(Ps[(mrow + g    ) * AST + kk + tg    ]);
            af[1] = __float_as_uint(Ps[(mrow + 8 + g) * AST + kk + tg    ]);
            af[2] = __float_as_uint(Ps[(mrow + g    ) * AST + kk + 4 + tg]);
            af[3] = __float_as_uint(Ps[(mrow + 8 + g) * AST + kk + 4 + tg]);
            #pragma unroll
            for (int nt = 0; nt < 8; nt++) {
                const int nb = nt * 8;
                uint32_t bf[2];
                bf[0] = __float_as_uint(Vt[(nb + g) * AST + kk + tg    ]);
                bf[1] = __float_as_uint(Vt[(nb + g) * AST + kk + 4 + tg]);
                mma8(o[nt], af, bf);
            }
        }
    }

    // epilogue: normalize, write [B,N,C] (c = h*64 + d)
    const int b = bh >> 4, h = bh & 15;
    const float inv0 = 1.f / ls[0], inv1 = 1.f / ls[1];
    float* op = AO + ((size_t)(b * N_ + q0 + mrow + g)) * C_ + h * D_;
    #pragma unroll
    for (int nt = 0; nt < 8; nt++) {
        const int col = nt * 8 + tg * 2;
        *(float2*)(op + col) = make_float2(o[nt][0] * inv0, o[nt][1] * inv0);
        *(float2*)(op + (size_t)8 * C_ + col) = make_float2(o[nt][2] * inv1, o[nt][3] * inv1);
    }
}

// =============================================================================
extern "C" void kernel_launch(void* const* d_in, const int* in_sizes, int n_in,
                              void* d_out, int out_size)
{
    const float* x      = (const float*)d_in[0];
    const float* qkv_w  = (const float*)d_in[1];
    const float* qkv_b  = (const float*)d_in[2];
    const float* qnw    = (const float*)d_in[3];
    const float* qnb    = (const float*)d_in[4];
    const float* knw    = (const float*)d_in[5];
    const float* knb    = (const float*)d_in[6];
    const float* proj_w = (const float*)d_in[7];
    const float* proj_b = (const float*)d_in[8];
    float* out = (float*)d_out;

    float *qkv, *q, *k, *v, *ao;
    cudaGetSymbolAddress((void**)&qkv, g_qkv);
    cudaGetSymbolAddress((void**)&q,   g_q);
    cudaGetSymbolAddress((void**)&k,   g_k);
    cudaGetSymbolAddress((void**)&v,   g_v);
    cudaGetSymbolAddress((void**)&ao,  g_ao);

    // 1) QKV projection: [8192,1024] @ [3072,1024]^T (tf32 tensor cores)
    {
        dim3 grid(3 * C_ / 128, (B_ * N_) / 128);
        gemm_tf32<<<grid, 256>>>(x, qkv_w, qkv_b, qkv, B_ * N_, 3 * C_, C_);
    }
    // 2) per-head LN + split
    {
        int warps = B_ * H_ * N_;
        ln_split<<<warps / 8, 256>>>(qkv, qnw, qnb, knw, knb, q, k, v);
    }
    // 3) attention (tf32 tensor cores)
    {
        const int smem = 384 * AST * (int)sizeof(float);  // 104448 B
        cudaFuncSetAttribute(attn_tf32, cudaFuncAttributeMaxDynamicSharedMemorySize, smem);
        dim3 grid(N_ / 128, BH_);
        attn_tf32<<<grid, 256, smem>>>(q, k, v, ao);
    }
    // 4) output projection -> d_out (tf32 tensor cores)
    {
        dim3 grid(C_ / 128, (B_ * N_) / 128);
        gemm_tf32<<<grid, 256>>>(ao, proj_w, proj_b, out, B_ * N_, C_, C_);
    }
}

// round 4
// speedup vs baseline: 4.8480x; 1.7457x over previous
#include <cuda_runtime.h>
#include <cuda_fp16.h>
#include <math.h>
#include <stdint.h>
#include <stddef.h>

#define B_  2
#define N_  4096
#define C_  1024
#define H_  16
#define D_  64
#define BH_ (B_*H_)

// ---------------- scratch (device globals; no allocs allowed) ----------------
__device__ float  g_qkv   [(size_t)B_*N_*3*C_];   // [B,N,3C] fp32
__device__ __half g_xh    [(size_t)B_*N_*C_];     // x in fp16
__device__ __half g_wqkv_h[(size_t)3*C_*C_];      // qkv_w fp16
__device__ __half g_wproj_h[(size_t)C_*C_];       // proj_w fp16
__device__ __half g_q [(size_t)BH_*N_*D_];        // [B,H,N,D] LN'd, pre-scaled
__device__ __half g_k [(size_t)BH_*N_*D_];
__device__ __half g_v [(size_t)BH_*N_*D_];
__device__ __half g_ao[(size_t)B_*N_*C_];         // [B,N,C] attention out fp16

// ---------------- helpers ----------------
__device__ __forceinline__ uint32_t packh2(float x, float y) {
    __half2 h = __floats2half2_rn(x, y);
    return *(uint32_t*)&h;
}

__device__ __forceinline__ void mma16(float* c, const uint32_t* a, const uint32_t* b) {
    asm volatile(
        "mma.sync.aligned.m16n8k16.row.col.f32.f16.f16.f32 "
        "{%0,%1,%2,%3}, {%4,%5,%6,%7}, {%8,%9}, {%0,%1,%2,%3};"
        : "+f"(c[0]), "+f"(c[1]), "+f"(c[2]), "+f"(c[3])
        : "r"(a[0]), "r"(a[1]), "r"(a[2]), "r"(a[3]), "r"(b[0]), "r"(b[1]));
}

#define CP_ASYNC16(dst_u32, src) \
    asm volatile("cp.async.cg.shared.global [%0], [%1], 16;" :: "r"(dst_u32), "l"(src))
#define CP_COMMIT() asm volatile("cp.async.commit_group;")
#define CP_WAIT(n)  asm volatile("cp.async.wait_group %0;" :: "n"(n))

// =============================================================================
// fp32 -> fp16 elementwise convert
// =============================================================================
__global__ __launch_bounds__(256) void f2h_kernel(const float* __restrict__ in,
                                                  __half* __restrict__ out, int n4)
{
    int i = blockIdx.x * blockDim.x + threadIdx.x;
    if (i >= n4) return;
    float4 v = ((const float4*)in)[i];
    uint32_t lo = packh2(v.x, v.y), hi = packh2(v.z, v.w);
    ((uint2*)out)[i] = make_uint2(lo, hi);
}

// =============================================================================
// fp16 tensor-core GEMM: C[M,Nout](fp32) = A[M,K](fp16) @ W[Nout,K](fp16)^T + b
// 128x128 block, BK=16, 3-stage cp.async pipeline, 8 warps (2x4), warp 64x32.
// =============================================================================
#define GST 24   // smem row stride in halves (16 + 8 pad)

__global__ __launch_bounds__(256) void gemm_h16(
    const __half* __restrict__ A, const __half* __restrict__ W,
    const float* __restrict__ bias, float* __restrict__ Cmat,
    int M, int Nout, int K)
{
    __shared__ __half As[3][128][GST];
    __shared__ __half Bs[3][128][GST];

    const int tid  = threadIdx.x;
    const int warp = tid >> 5, lane = tid & 31;
    const int mw   = warp >> 2, nw = warp & 3;
    const int g    = lane >> 2, tg = lane & 3;
    const int bm   = blockIdx.y * 128, bn = blockIdx.x * 128;

    const int lrow = tid >> 1;            // 0..127
    const int lc8  = (tid & 1) * 8;       // 0 or 8 (halves)

    const __half* Ap = A + (size_t)(bm + lrow) * K + lc8;
    const __half* Wp = W + (size_t)(bn + lrow) * K + lc8;

    const int T = K / 16;

    auto issue = [&](int it) {
        const int st = it % 3;
        uint32_t da = (uint32_t)__cvta_generic_to_shared(&As[st][lrow][lc8]);
        uint32_t db = (uint32_t)__cvta_generic_to_shared(&Bs[st][lrow][lc8]);
        CP_ASYNC16(da, Ap + it * 16);
        CP_ASYNC16(db, Wp + it * 16);
        CP_COMMIT();
    };

    float acc[4][4][4];
    #pragma unroll
    for (int i = 0; i < 4; i++)
        #pragma unroll
        for (int j = 0; j < 4; j++)
            #pragma unroll
            for (int e = 0; e < 4; e++) acc[i][j][e] = 0.f;

    issue(0);
    issue(1);

    for (int it = 0; it < T; it++) {
        if (it == T - 1) { CP_WAIT(0); } else { CP_WAIT(1); }
        __syncthreads();
        if (it + 2 < T) issue(it + 2);

        const int st = it % 3;
        uint32_t a[4][4];
        #pragma unroll
        for (int mt = 0; mt < 4; mt++) {
            const int rb = mw * 64 + mt * 16;
            a[mt][0] = *(const uint32_t*)&As[st][rb + g    ][2*tg    ];
            a[mt][1] = *(const uint32_t*)&As[st][rb + 8 + g][2*tg    ];
            a[mt][2] = *(const uint32_t*)&As[st][rb + g    ][2*tg + 8];
            a[mt][3] = *(const uint32_t*)&As[st][rb + 8 + g][2*tg + 8];
        }
        uint32_t b[4][2];
        #pragma unroll
        for (int nt = 0; nt < 4; nt++) {
            const int nb = nw * 32 + nt * 8;
            b[nt][0] = *(const uint32_t*)&Bs[st][nb + g][2*tg    ];
            b[nt][1] = *(const uint32_t*)&Bs[st][nb + g][2*tg + 8];
        }
        #pragma unroll
        for (int mt = 0; mt < 4; mt++)
            #pragma unroll
            for (int nt = 0; nt < 4; nt++)
                mma16(acc[mt][nt], a[mt], b[nt]);
        __syncthreads();
    }

    #pragma unroll
    for (int mt = 0; mt < 4; mt++) {
        const int row0 = bm + mw * 64 + mt * 16 + g;
        #pragma unroll
        for (int nt = 0; nt < 4; nt++) {
            const int col = bn + nw * 32 + nt * 8 + 2 * tg;
            const float b0 = bias[col], b1 = bias[col + 1];
            *(float2*)(Cmat + (size_t)row0 * Nout + col) =
                make_float2(acc[mt][nt][0] + b0, acc[mt][nt][1] + b1);
            *(float2*)(Cmat + (size_t)(row0 + 8) * Nout + col) =
                make_float2(acc[mt][nt][2] + b0, acc[mt][nt][3] + b1);
        }
    }
}

// =============================================================================
// LayerNorm over D=64 per (b,h,n) for q,k + v copy; fp16 outputs. q pre-scaled.
// =============================================================================
__global__ __launch_bounds__(256) void ln_split(
    const float* __restrict__ qkv,
    const float* __restrict__ qw, const float* __restrict__ qb,
    const float* __restrict__ kw, const float* __restrict__ kb,
    __half* __restrict__ Qo, __half* __restrict__ Ko, __half* __restrict__ Vo)
{
    const int gw   = (blockIdx.x * blockDim.x + threadIdx.x) >> 5;
    const int lane = threadIdx.x & 31;
    const int n = gw & (N_ - 1);
    const int h = (gw >> 12) & (H_ - 1);
    const int b = gw >> 16;

    const float* base = qkv + ((size_t)(b * N_ + n)) * (3 * C_) + h * D_;
    const size_t oidx = ((size_t)((b * H_ + h) * N_) + n) * D_ + lane * 2;
    const int d = lane * 2;

    float2 vv = *(const float2*)(base + 2 * C_ + d);
    *(__half2*)(Vo + oidx) = __floats2half2_rn(vv.x, vv.y);

    const float inv64 = 1.f / 64.f;
    {
        float2 qv = *(const float2*)(base + d);
        float s = qv.x + qv.y, ss = qv.x*qv.x + qv.y*qv.y;
        #pragma unroll
        for (int m = 16; m; m >>= 1) {
            s  += __shfl_xor_sync(0xffffffffu, s,  m);
            ss += __shfl_xor_sync(0xffffffffu, ss, m);
        }
        float mu = s * inv64;
        float var = fmaxf(ss * inv64 - mu * mu, 0.f);
        float rstd = rsqrtf(var + 1e-5f);
        const float sc = 0.125f;  // D^-0.5
        float rx = ((qv.x - mu) * rstd * qw[d]     + qb[d])     * sc;
        float ry = ((qv.y - mu) * rstd * qw[d + 1] + qb[d + 1]) * sc;
        *(__half2*)(Qo + oidx) = __floats2half2_rn(rx, ry);
    }
    {
        float2 kv = *(const float2*)(base + C_ + d);
        float s = kv.x + kv.y, ss = kv.x*kv.x + kv.y*kv.y;
        #pragma unroll
        for (int m = 16; m; m >>= 1) {
            s  += __shfl_xor_sync(0xffffffffu, s,  m);
            ss += __shfl_xor_sync(0xffffffffu, ss, m);
        }
        float mu = s * inv64;
        float var = fmaxf(ss * inv64 - mu * mu, 0.f);
        float rstd = rsqrtf(var + 1e-5f);
        float rx = (kv.x - mu) * rstd * kw[d]     + kb[d];
        float ry = (kv.y - mu) * rstd * kw[d + 1] + kb[d + 1];
        *(__half2*)(Ko + oidx) = __floats2half2_rn(rx, ry);
    }
}

// =============================================================================
// Flash attention, fp16 MMA. Block = 128 q-rows of one (b,h), 8 warps (16 rows
// each). Q-frags register-resident, K/V register-double-buffered, P in regs.
// =============================================================================
#define AST2 72  // smem row stride in halves (64 + 8 pad)

__global__ __launch_bounds__(256) void attn_h16(
    const __half* __restrict__ Q, const __half* __restrict__ Kg,
    const __half* __restrict__ Vg, __half* __restrict__ AO)
{
    extern __shared__ __half sh[];
    __half* Qs = sh;                      // [128][AST2]
    __half* Ks = Qs + 128 * AST2;         // [2][64][AST2]
    __half* Vt = Ks + 2 * 64 * AST2;      // [2][64][AST2]  V^T: [d][key]

    const int tid  = threadIdx.x;
    const int warp = tid >> 5, lane = tid & 31;
    const int g    = lane >> 2, tg = lane & 3;
    const int bh   = blockIdx.y;
    const int q0   = blockIdx.x * 128;
    const int mrow = warp * 16;

    const __half* Qb = Q  + ((size_t)bh * N_ + q0) * D_;
    const __half* Kb = Kg + (size_t)bh * N_ * D_;
    const __half* Vb = Vg + (size_t)bh * N_ * D_;

    // ---- load Q tile (128x64 halves) ----
    #pragma unroll
    for (int j = 0; j < 4; j++) {
        const int id  = tid + 256 * j;
        const int row = id >> 3;
        const int c8  = (id & 7) * 8;
        *(uint4*)&Qs[row * AST2 + c8] = *(const uint4*)(Qb + (size_t)row * D_ + c8);
    }

    // ---- load K/V tile 0 into regs, store to stage 0 ----
    uint4 kp[2], vp[2];
    #pragma unroll
    for (int j = 0; j < 2; j++) {
        const int id  = tid + 256 * j;
        const int row = id >> 3, c8 = (id & 7) * 8;
        kp[j] = *(const uint4*)(Kb + (size_t)row * D_ + c8);
        vp[j] = *(const uint4*)(Vb + (size_t)row * D_ + c8);
    }
    #pragma unroll
    for (int j = 0; j < 2; j++) {
        const int id  = tid + 256 * j;
        const int row = id >> 3, c8 = (id & 7) * 8;
        *(uint4*)&Ks[row * AST2 + c8] = kp[j];
        const __half* hv = (const __half*)&vp[j];
        #pragma unroll
        for (int i = 0; i < 8; i++) Vt[(c8 + i) * AST2 + row] = hv[i];
    }
    __syncthreads();

    // ---- Q fragments, register resident for all tiles ----
    uint32_t qf[4][4];
    #pragma unroll
    for (int ks = 0; ks < 4; ks++) {
        const int kk = ks * 16;
        qf[ks][0] = *(const uint32_t*)&Qs[(mrow + g    ) * AST2 + kk + 2*tg    ];
        qf[ks][1] = *(const uint32_t*)&Qs[(mrow + 8 + g) * AST2 + kk + 2*tg    ];
        qf[ks][2] = *(const uint32_t*)&Qs[(mrow + g    ) * AST2 + kk + 2*tg + 8];
        qf[ks][3] = *(const uint32_t*)&Qs[(mrow + 8 + g) * AST2 + kk + 2*tg + 8];
    }

    float o[8][4];
    #pragma unroll
    for (int nt = 0; nt < 8; nt++)
        #pragma unroll
        for (int e = 0; e < 4; e++) o[nt][e] = 0.f;
    float ms[2] = { -1e30f, -1e30f };
    float ls[2] = { 0.f, 0.f };

    const int T = N_ / 64;
    for (int t = 0; t < T; t++) {
        const int cur = t & 1, nxt = cur ^ 1;
        __half* Kc = Ks + cur * 64 * AST2;
        __half* Vc = Vt + cur * 64 * AST2;

        // prefetch next K/V tiles into regs
        if (t + 1 < T) {
            #pragma unroll
            for (int j = 0; j < 2; j++) {
                const int id  = tid + 256 * j;
                const int row = id >> 3, c8 = (id & 7) * 8;
                kp[j] = *(const uint4*)(Kb + (size_t)((t+1) * 64 + row) * D_ + c8);
                vp[j] = *(const uint4*)(Vb + (size_t)((t+1) * 64 + row) * D_ + c8);
            }
        }

        // ---- S = Q @ K^T (warp: 16x64) ----
        float sacc[8][4];
        #pragma unroll
        for (int nt = 0; nt < 8; nt++)
            #pragma unroll
            for (int e = 0; e < 4; e++) sacc[nt][e] = 0.f;

        #pragma unroll
        for (int ks = 0; ks < 4; ks++) {
            const int kk = ks * 16;
            #pragma unroll
            for (int nt = 0; nt < 8; nt++) {
                uint32_t b[2];
                b[0] = *(const uint32_t*)&Kc[(nt*8 + g) * AST2 + kk + 2*tg    ];
                b[1] = *(const uint32_t*)&Kc[(nt*8 + g) * AST2 + kk + 2*tg + 8];
                mma16(sacc[nt], qf[ks], b);
            }
        }

        // ---- online softmax (rows mrow+g, mrow+8+g) ----
        #pragma unroll
        for (int hh = 0; hh < 2; hh++) {
            float mx = -1e30f;
            #pragma unroll
            for (int nt = 0; nt < 8; nt++)
                mx = fmaxf(mx, fmaxf(sacc[nt][2*hh], sacc[nt][2*hh+1]));
            mx = fmaxf(mx, __shfl_xor_sync(0xffffffffu, mx, 1));
            mx = fmaxf(mx, __shfl_xor_sync(0xffffffffu, mx, 2));
            const float mn   = fmaxf(ms[hh], mx);
            const float corr = __expf(ms[hh] - mn);
            ms[hh] = mn;
            float sum = 0.f;
            #pragma unroll
            for (int nt = 0; nt < 8; nt++) {
                float p0 = __expf(sacc[nt][2*hh]     - mn);
                float p1 = __expf(sacc[nt][2*hh + 1] - mn);
                sacc[nt][2*hh] = p0; sacc[nt][2*hh+1] = p1;
                sum += p0 + p1;
            }
            sum += __shfl_xor_sync(0xffffffffu, sum, 1);
            sum += __shfl_xor_sync(0xffffffffu, sum, 2);
            ls[hh] = ls[hh] * corr + sum;
            #pragma unroll
            for (int nt = 0; nt < 8; nt++) {
                o[nt][2*hh]   *= corr;
                o[nt][2*hh+1] *= corr;
            }
        }

        // ---- O += P @ V : P-frags straight from sacc registers ----
        #pragma unroll
        for (int ks = 0; ks < 4; ks++) {
            uint32_t a[4];
            a[0] = packh2(sacc[2*ks    ][0], sacc[2*ks    ][1]);
            a[1] = packh2(sacc[2*ks    ][2], sacc[2*ks    ][3]);
            a[2] = packh2(sacc[2*ks + 1][0], sacc[2*ks + 1][1]);
            a[3] = packh2(sacc[2*ks + 1][2], sacc[2*ks + 1][3]);
            const int kk = ks * 16;
            #pragma unroll
            for (int nt = 0; nt < 8; nt++) {
                uint32_t b[2];
                b[0] = *(const uint32_t*)&Vc[(nt*8 + g) * AST2 + kk + 2*tg    ];
                b[1] = *(const uint32_t*)&Vc[(nt*8 + g) * AST2 + kk + 2*tg + 8];
                mma16(o[nt], a, b);
            }
        }

        // ---- store prefetched tiles to next stage ----
        if (t + 1 < T) {
            __half* Kn = Ks + nxt * 64 * AST2;
            __half* Vn = Vt + nxt * 64 * AST2;
            #pragma unroll
            for (int j = 0; j < 2; j++) {
                const int id  = tid + 256 * j;
                const int row = id >> 3, c8 = (id & 7) * 8;
                *(uint4*)&Kn[row * AST2 + c8] = kp[j];
                const __half* hv = (const __half*)&vp[j];
                #pragma unroll
                for (int i = 0; i < 8; i++) Vn[(c8 + i) * AST2 + row] = hv[i];
            }
        }
        __syncthreads();
    }

    // ---- epilogue: normalize, write fp16 [B,N,C] ----
    const int b = bh >> 4, h = bh & 15;
    const float inv0 = 1.f / ls[0], inv1 = 1.f / ls[1];
    __half* op = AO + ((size_t)(b * N_ + q0 + mrow + g)) * C_ + h * D_;
    #pragma unroll
    for (int nt = 0; nt < 8; nt++) {
        const int col = nt * 8 + 2 * tg;
        *(__half2*)(op + col) = __floats2half2_rn(o[nt][0] * inv0, o[nt][1] * inv0);
        *(__half2*)(op + (size_t)8 * C_ + col) =
            __floats2half2_rn(o[nt][2] * inv1, o[nt][3] * inv1);
    }
}

// =============================================================================
extern "C" void kernel_launch(void* const* d_in, const int* in_sizes, int n_in,
                              void* d_out, int out_size)
{
    const float* x      = (const float*)d_in[0];
    const float* qkv_w  = (const float*)d_in[1];
    const float* qkv_b  = (const float*)d_in[2];
    const float* qnw    = (const float*)d_in[3];
    const float* qnb    = (const float*)d_in[4];
    const float* knw    = (const float*)d_in[5];
    const float* knb    = (const float*)d_in[6];
    const float* proj_w = (const float*)d_in[7];
    const float* proj_b = (const float*)d_in[8];
    float* out = (float*)d_out;

    float *qkv; __half *xh, *wqkv, *wproj, *q, *k, *v, *ao;
    cudaGetSymbolAddress((void**)&qkv,   g_qkv);
    cudaGetSymbolAddress((void**)&xh,    g_xh);
    cudaGetSymbolAddress((void**)&wqkv,  g_wqkv_h);
    cudaGetSymbolAddress((void**)&wproj, g_wproj_h);
    cudaGetSymbolAddress((void**)&q,     g_q);
    cudaGetSymbolAddress((void**)&k,     g_k);
    cudaGetSymbolAddress((void**)&v,     g_v);
    cudaGetSymbolAddress((void**)&ao,    g_ao);

    // 0) fp16 preconversion of x and weights
    {
        int n4x = (B_ * N_ * C_) / 4;
        f2h_kernel<<<(n4x + 255) / 256, 256>>>(x, xh, n4x);
        int n4w = (3 * C_ * C_) / 4;
        f2h_kernel<<<(n4w + 255) / 256, 256>>>(qkv_w, wqkv, n4w);
        int n4p = (C_ * C_) / 4;
        f2h_kernel<<<(n4p + 255) / 256, 256>>>(proj_w, wproj, n4p);
    }
    // 1) QKV projection (fp16 MMA, cp.async pipeline)
    {
        dim3 grid(3 * C_ / 128, (B_ * N_) / 128);
        gemm_h16<<<grid, 256>>>(xh, wqkv, qkv_b, qkv, B_ * N_, 3 * C_, C_);
    }
    // 2) per-head LN + split -> fp16
    {
        int warps = B_ * H_ * N_;
        ln_split<<<warps / 8, 256>>>(qkv, qnw, qnb, knw, knb, q, k, v);
    }
    // 3) attention (fp16 MMA)
    {
        const int smem = (128 + 4 * 64) * AST2 * (int)sizeof(__half);  // 55296
        cudaFuncSetAttribute(attn_h16, cudaFuncAttributeMaxDynamicSharedMemorySize, smem);
        dim3 grid(N_ / 128, BH_);
        attn_h16<<<grid, 256, smem>>>(q, k, v, ao);
    }
    // 4) output projection -> d_out (fp16 MMA)
    {
        dim3 grid(C_ / 128, (B_ * N_) / 128);
        gemm_h16<<<grid, 256>>>(ao, wproj, proj_b, out, B_ * N_, C_, C_);
    }
}

// round 6
// speedup vs baseline: 6.8063x; 1.4039x over previous
#include <cuda_runtime.h>
#include <cuda_fp16.h>
#include <math.h>
#include <stdint.h>
#include <stddef.h>

#define B_  2
#define N_  4096
#define C_  1024
#define H_  16
#define D_  64
#define BH_ (B_*H_)

// ---------------- scratch (device globals; no allocs allowed) ----------------
__device__ float  g_qkv   [(size_t)B_*N_*3*C_];   // [B,N,3C] fp32
__device__ __half g_xh    [(size_t)B_*N_*C_];     // x in fp16
__device__ __half g_wqkv_h[(size_t)3*C_*C_];      // qkv_w fp16
__device__ __half g_wproj_h[(size_t)C_*C_];       // proj_w fp16
__device__ __half g_q [(size_t)BH_*N_*D_];        // [B,H,N,D] LN'd, pre-scaled
__device__ __half g_k [(size_t)BH_*N_*D_];
__device__ __half g_v [(size_t)BH_*N_*D_];
__device__ __half g_ao[(size_t)B_*N_*C_];         // [B,N,C] attention out fp16

// ---------------- helpers ----------------
__device__ __forceinline__ uint32_t packh2(float x, float y) {
    __half2 h = __floats2half2_rn(x, y);
    return *(uint32_t*)&h;
}
__device__ __forceinline__ uint32_t saddr(const void* p) {
    return (uint32_t)__cvta_generic_to_shared(p);
}

__device__ __forceinline__ void mma16(float* c, const uint32_t* a, const uint32_t* b) {
    asm volatile(
        "mma.sync.aligned.m16n8k16.row.col.f32.f16.f16.f32 "
        "{%0,%1,%2,%3}, {%4,%5,%6,%7}, {%8,%9}, {%0,%1,%2,%3};"
        : "+f"(c[0]), "+f"(c[1]), "+f"(c[2]), "+f"(c[3])
        : "r"(a[0]), "r"(a[1]), "r"(a[2]), "r"(a[3]), "r"(b[0]), "r"(b[1]));
}

#define LDSM_X4(R0,R1,R2,R3,ADDR) \
    asm volatile("ldmatrix.sync.aligned.m8n8.x4.shared.b16 {%0,%1,%2,%3}, [%4];" \
        : "=r"(R0), "=r"(R1), "=r"(R2), "=r"(R3) : "r"(ADDR))
#define LDSM_X4T(R0,R1,R2,R3,ADDR) \
    asm volatile("ldmatrix.sync.aligned.m8n8.x4.trans.shared.b16 {%0,%1,%2,%3}, [%4];" \
        : "=r"(R0), "=r"(R1), "=r"(R2), "=r"(R3) : "r"(ADDR))

#define CP_ASYNC16(dst_u32, src) \
    asm volatile("cp.async.cg.shared.global [%0], [%1], 16;" :: "r"(dst_u32), "l"(src))
#define CP_COMMIT() asm volatile("cp.async.commit_group;")
#define CP_WAIT(n)  asm volatile("cp.async.wait_group %0;" :: "n"(n))

// =============================================================================
// fp32 -> fp16 elementwise convert
// =============================================================================
__global__ __launch_bounds__(256) void f2h_kernel(const float* __restrict__ in,
                                                  __half* __restrict__ out, int n4)
{
    int i = blockIdx.x * blockDim.x + threadIdx.x;
    if (i >= n4) return;
    float4 v = ((const float4*)in)[i];
    ((uint2*)out)[i] = make_uint2(packh2(v.x, v.y), packh2(v.z, v.w));
}

// =============================================================================
// fp16 GEMM: C[M,Nout](fp32) = A[M,K](fp16) @ W[Nout,K](fp16)^T + bias
// 128x128 tile, BK=32, 3-stage cp.async, ldmatrix frags, 8 warps (2x4).
// =============================================================================
#define GST 40   // smem row stride in halves (32 + 8 pad); 80B rows

__global__ __launch_bounds__(256, 2) void gemm_h16(
    const __half* __restrict__ A, const __half* __restrict__ W,
    const float* __restrict__ bias, float* __restrict__ Cmat,
    int M, int Nout, int K)
{
    extern __shared__ __half sg[];
    __half* As = sg;                   // [3][128][GST]
    __half* Bs = sg + 3 * 128 * GST;   // [3][128][GST]

    const int tid  = threadIdx.x;
    const int warp = tid >> 5, lane = tid & 31;
    const int mw   = warp >> 2, nw = warp & 3;
    const int g    = lane >> 2, tg = lane & 3;
    const int bm   = blockIdx.y * 128, bn = blockIdx.x * 128;

    // ldmatrix per-lane offsets
    const int aR = (lane & 7) + ((lane >> 3) & 1) * 8;   // A/non-trans row off
    const int aC = (lane >> 4) * 8;                      // A col off
    const int bR = (lane & 7) + (lane >> 4) * 8;         // B row off
    const int bC = ((lane >> 3) & 1) * 8;                // B col off

    const int lrow = tid >> 2;            // 0..63
    const int lc8  = (tid & 3) * 8;       // 0,8,16,24 halves

    const __half* Ap = A + (size_t)(bm + lrow) * K + lc8;
    const __half* Wp = W + (size_t)(bn + lrow) * K + lc8;

    const int T = K / 32;

    auto issue = [&](int it) {
        const int st = it % 3;
        __half* as = As + st * 128 * GST;
        __half* bs = Bs + st * 128 * GST;
        CP_ASYNC16(saddr(&as[lrow * GST + lc8]),        Ap + it * 32);
        CP_ASYNC16(saddr(&as[(lrow + 64) * GST + lc8]), Ap + (size_t)64 * K + it * 32);
        CP_ASYNC16(saddr(&bs[lrow * GST + lc8]),        Wp + it * 32);
        CP_ASYNC16(saddr(&bs[(lrow + 64) * GST + lc8]), Wp + (size_t)64 * K + it * 32);
        CP_COMMIT();
    };

    float acc[4][4][4];
    #pragma unroll
    for (int i = 0; i < 4; i++)
        #pragma unroll
        for (int j = 0; j < 4; j++)
            #pragma unroll
            for (int e = 0; e < 4; e++) acc[i][j][e] = 0.f;

    issue(0);
    issue(1);

    for (int it = 0; it < T; it++) {
        if (it < T - 1) { CP_WAIT(1); } else { CP_WAIT(0); }
        __syncthreads();
        if (it + 2 < T) issue(it + 2);

        const int st = it % 3;
        __half* as = As + st * 128 * GST;
        __half* bs = Bs + st * 128 * GST;

        #pragma unroll
        for (int ks = 0; ks < 2; ks++) {
            const int kk = ks * 16;
            uint32_t a[4][4], b[4][2];
            #pragma unroll
            for (int mt = 0; mt < 4; mt++)
                LDSM_X4(a[mt][0], a[mt][1], a[mt][2], a[mt][3],
                        saddr(&as[(mw * 64 + mt * 16 + aR) * GST + kk + aC]));
            #pragma unroll
            for (int np = 0; np < 2; np++) {
                uint32_t r0, r1, r2, r3;
                LDSM_X4(r0, r1, r2, r3,
                        saddr(&bs[(nw * 32 + np * 16 + bR) * GST + kk + bC]));
                b[2*np][0] = r0; b[2*np][1] = r1;
                b[2*np+1][0] = r2; b[2*np+1][1] = r3;
            }
            #pragma unroll
            for (int mt = 0; mt < 4; mt++)
                #pragma unroll
                for (int nt = 0; nt < 4; nt++)
                    mma16(acc[mt][nt], a[mt], b[nt]);
        }
    }

    #pragma unroll
    for (int mt = 0; mt < 4; mt++) {
        const int row0 = bm + mw * 64 + mt * 16 + g;
        #pragma unroll
        for (int nt = 0; nt < 4; nt++) {
            const int col = bn + nw * 32 + nt * 8 + 2 * tg;
            const float b0 = bias[col], b1 = bias[col + 1];
            *(float2*)(Cmat + (size_t)row0 * Nout + col) =
                make_float2(acc[mt][nt][0] + b0, acc[mt][nt][1] + b1);
            *(float2*)(Cmat + (size_t)(row0 + 8) * Nout + col) =
                make_float2(acc[mt][nt][2] + b0, acc[mt][nt][3] + b1);
        }
    }
}

// =============================================================================
// LayerNorm over D=64 per (b,h,n) for q,k + v copy; fp16 outputs. q pre-scaled.
// =============================================================================
__global__ __launch_bounds__(256) void ln_split(
    const float* __restrict__ qkv,
    const float* __restrict__ qw, const float* __restrict__ qb,
    const float* __restrict__ kw, const float* __restrict__ kb,
    __half* __restrict__ Qo, __half* __restrict__ Ko, __half* __restrict__ Vo)
{
    const int gw   = (blockIdx.x * blockDim.x + threadIdx.x) >> 5;
    const int lane = threadIdx.x & 31;
    const int n = gw & (N_ - 1);
    const int h = (gw >> 12) & (H_ - 1);
    const int b = gw >> 16;

    const float* base = qkv + ((size_t)(b * N_ + n)) * (3 * C_) + h * D_;
    const size_t oidx = ((size_t)((b * H_ + h) * N_) + n) * D_ + lane * 2;
    const int d = lane * 2;

    float2 vv = *(const float2*)(base + 2 * C_ + d);
    *(__half2*)(Vo + oidx) = __floats2half2_rn(vv.x, vv.y);

    const float inv64 = 1.f / 64.f;
    {
        float2 qv = *(const float2*)(base + d);
        float s = qv.x + qv.y, ss = qv.x*qv.x + qv.y*qv.y;
        #pragma unroll
        for (int m = 16; m; m >>= 1) {
            s  += __shfl_xor_sync(0xffffffffu, s,  m);
            ss += __shfl_xor_sync(0xffffffffu, ss, m);
        }
        float mu = s * inv64;
        float var = fmaxf(ss * inv64 - mu * mu, 0.f);
        float rstd = rsqrtf(var + 1e-5f);
        const float sc = 0.125f;  // D^-0.5
        float rx = ((qv.x - mu) * rstd * qw[d]     + qb[d])     * sc;
        float ry = ((qv.y - mu) * rstd * qw[d + 1] + qb[d + 1]) * sc;
        *(__half2*)(Qo + oidx) = __floats2half2_rn(rx, ry);
    }
    {
        float2 kv = *(const float2*)(base + C_ + d);
        float s = kv.x + kv.y, ss = kv.x*kv.x + kv.y*kv.y;
        #pragma unroll
        for (int m = 16; m; m >>= 1) {
            s  += __shfl_xor_sync(0xffffffffu, s,  m);
            ss += __shfl_xor_sync(0xffffffffu, ss, m);
        }
        float mu = s * inv64;
        float var = fmaxf(ss * inv64 - mu * mu, 0.f);
        float rstd = rsqrtf(var + 1e-5f);
        float rx = (kv.x - mu) * rstd * kw[d]     + kb[d];
        float ry = (kv.y - mu) * rstd * kw[d + 1] + kb[d + 1];
        *(__half2*)(Ko + oidx) = __floats2half2_rn(rx, ry);
    }
}

// =============================================================================
// Flash attention, fp16 MMA. 128 q-rows/CTA, 8 warps x 16 rows. Bc=64 keys.
// K/V via 3-stage cp.async (FULL 64x64 tiles); K frags via ldmatrix;
// V^T via ldmatrix.trans. P stays in registers. Q frags register-resident.
// =============================================================================
#define AST2 72  // smem row stride in halves (64 + 8 pad); 144B rows

__global__ __launch_bounds__(256, 2) void attn_h16(
    const __half* __restrict__ Q, const __half* __restrict__ Kg,
    const __half* __restrict__ Vg, __half* __restrict__ AO)
{
    extern __shared__ __half sh[];
    __half* Qs = sh;                      // [128][AST2]
    __half* Ks = Qs + 128 * AST2;         // [3][64][AST2]
    __half* Vs = Ks + 3 * 64 * AST2;      // [3][64][AST2]

    const int tid  = threadIdx.x;
    const int warp = tid >> 5, lane = tid & 31;
    const int g    = lane >> 2, tg = lane & 3;
    const int bh   = blockIdx.y;
    const int q0   = blockIdx.x * 128;
    const int mrow = warp * 16;

    const int aR = (lane & 7) + ((lane >> 3) & 1) * 8;
    const int aC = (lane >> 4) * 8;
    const int bR = (lane & 7) + (lane >> 4) * 8;
    const int bC = ((lane >> 3) & 1) * 8;

    const __half* Qb = Q  + ((size_t)bh * N_ + q0) * D_;
    const __half* Kb = Kg + (size_t)bh * N_ * D_;
    const __half* Vb = Vg + (size_t)bh * N_ * D_;

    // ---- load Q tile (128x64 halves) ----
    #pragma unroll
    for (int j = 0; j < 4; j++) {
        const int id  = tid + 256 * j;
        const int row = id >> 3;
        const int c8  = (id & 7) * 8;
        *(uint4*)&Qs[row * AST2 + c8] = *(const uint4*)(Qb + (size_t)row * D_ + c8);
    }

    const int lrow = tid >> 2;            // 0..63
    const int lc8  = (tid & 3) * 8;       // 0,8,16,24

    // full 64x64 tile per tensor: each thread copies 2 column chunks per row
    auto issueKV = [&](int t) {
        const int st = t % 3;
        const __half* kp = Kb + (size_t)(t * 64 + lrow) * D_ + lc8;
        const __half* vp = Vb + (size_t)(t * 64 + lrow) * D_ + lc8;
        __half* ks = &Ks[(st * 64 + lrow) * AST2 + lc8];
        __half* vs = &Vs[(st * 64 + lrow) * AST2 + lc8];
        CP_ASYNC16(saddr(ks),      kp);
        CP_ASYNC16(saddr(ks + 32), kp + 32);
        CP_ASYNC16(saddr(vs),      vp);
        CP_ASYNC16(saddr(vs + 32), vp + 32);
        CP_COMMIT();
    };

    issueKV(0);
    issueKV(1);
    __syncthreads();   // Q stores visible

    // ---- Q fragments, register resident ----
    uint32_t qf[4][4];
    #pragma unroll
    for (int ks = 0; ks < 4; ks++)
        LDSM_X4(qf[ks][0], qf[ks][1], qf[ks][2], qf[ks][3],
                saddr(&Qs[(mrow + aR) * AST2 + ks * 16 + aC]));

    float o[8][4];
    #pragma unroll
    for (int nt = 0; nt < 8; nt++)
        #pragma unroll
        for (int e = 0; e < 4; e++) o[nt][e] = 0.f;
    float ms[2] = { -1e30f, -1e30f };
    float ls[2] = { 0.f, 0.f };

    const int T = N_ / 64;
    for (int t = 0; t < T; t++) {
        if (t < T - 1) { CP_WAIT(1); } else { CP_WAIT(0); }
        __syncthreads();
        if (t + 2 < T) issueKV(t + 2);

        const int st = t % 3;
        const __half* Kc = Ks + st * 64 * AST2;
        const __half* Vc = Vs + st * 64 * AST2;

        // ---- S = Q @ K^T (warp: 16x64) ----
        float sacc[8][4];
        #pragma unroll
        for (int nt = 0; nt < 8; nt++)
            #pragma unroll
            for (int e = 0; e < 4; e++) sacc[nt][e] = 0.f;

        #pragma unroll
        for (int ks = 0; ks < 4; ks++) {
            const int kk = ks * 16;
            #pragma unroll
            for (int np = 0; np < 4; np++) {
                uint32_t r0, r1, r2, r3;
                LDSM_X4(r0, r1, r2, r3,
                        saddr(&Kc[(np * 16 + bR) * AST2 + kk + bC]));
                uint32_t b0[2] = { r0, r1 }, b1[2] = { r2, r3 };
                mma16(sacc[2*np],     qf[ks], b0);
                mma16(sacc[2*np + 1], qf[ks], b1);
            }
        }

        // ---- online softmax (rows mrow+g, mrow+8+g) ----
        #pragma unroll
        for (int hh = 0; hh < 2; hh++) {
            float mx = -1e30f;
            #pragma unroll
            for (int nt = 0; nt < 8; nt++)
                mx = fmaxf(mx, fmaxf(sacc[nt][2*hh], sacc[nt][2*hh+1]));
            mx = fmaxf(mx, __shfl_xor_sync(0xffffffffu, mx, 1));
            mx = fmaxf(mx, __shfl_xor_sync(0xffffffffu, mx, 2));
            const float mn   = fmaxf(ms[hh], mx);
            const float corr = __expf(ms[hh] - mn);
            ms[hh] = mn;
            float sum = 0.f;
            #pragma unroll
            for (int nt = 0; nt < 8; nt++) {
                float p0 = __expf(sacc[nt][2*hh]     - mn);
                float p1 = __expf(sacc[nt][2*hh + 1] - mn);
                sacc[nt][2*hh] = p0; sacc[nt][2*hh+1] = p1;
                sum += p0 + p1;
            }
            sum += __shfl_xor_sync(0xffffffffu, sum, 1);
            sum += __shfl_xor_sync(0xffffffffu, sum, 2);
            ls[hh] = ls[hh] * corr + sum;
            #pragma unroll
            for (int nt = 0; nt < 8; nt++) {
                o[nt][2*hh]   *= corr;
                o[nt][2*hh+1] *= corr;
            }
        }

        // ---- O += P @ V : P from regs, V^T via ldmatrix.trans ----
        #pragma unroll
        for (int ks = 0; ks < 4; ks++) {
            const int kk = ks * 16;
            uint32_t a[4];
            a[0] = packh2(sacc[2*ks    ][0], sacc[2*ks    ][1]);
            a[1] = packh2(sacc[2*ks    ][2], sacc[2*ks    ][3]);
            a[2] = packh2(sacc[2*ks + 1][0], sacc[2*ks + 1][1]);
            a[3] = packh2(sacc[2*ks + 1][2], sacc[2*ks + 1][3]);
            #pragma unroll
            for (int dp = 0; dp < 4; dp++) {
                uint32_t r0, r1, r2, r3;
                LDSM_X4T(r0, r1, r2, r3,
                         saddr(&Vc[(kk + aR) * AST2 + dp * 16 + aC]));
                uint32_t b0[2] = { r0, r1 }, b1[2] = { r2, r3 };
                mma16(o[2*dp],     a, b0);
                mma16(o[2*dp + 1], a, b1);
            }
        }
    }

    // ---- epilogue: normalize, write fp16 [B,N,C] ----
    const int b = bh >> 4, h = bh & 15;
    const float inv0 = 1.f / ls[0], inv1 = 1.f / ls[1];
    __half* op = AO + ((size_t)(b * N_ + q0 + mrow + g)) * C_ + h * D_;
    #pragma unroll
    for (int nt = 0; nt < 8; nt++) {
        const int col = nt * 8 + 2 * tg;
        *(__half2*)(op + col) = __floats2half2_rn(o[nt][0] * inv0, o[nt][1] * inv0);
        *(__half2*)(op + (size_t)8 * C_ + col) =
            __floats2half2_rn(o[nt][2] * inv1, o[nt][3] * inv1);
    }
}

// =============================================================================
extern "C" void kernel_launch(void* const* d_in, const int* in_sizes, int n_in,
                              void* d_out, int out_size)
{
    const float* x      = (const float*)d_in[0];
    const float* qkv_w  = (const float*)d_in[1];
    const float* qkv_b  = (const float*)d_in[2];
    const float* qnw    = (const float*)d_in[3];
    const float* qnb    = (const float*)d_in[4];
    const float* knw    = (const float*)d_in[5];
    const float* knb    = (const float*)d_in[6];
    const float* proj_w = (const float*)d_in[7];
    const float* proj_b = (const float*)d_in[8];
    float* out = (float*)d_out;

    float *qkv; __half *xh, *wqkv, *wproj, *q, *k, *v, *ao;
    cudaGetSymbolAddress((void**)&qkv,   g_qkv);
    cudaGetSymbolAddress((void**)&xh,    g_xh);
    cudaGetSymbolAddress((void**)&wqkv,  g_wqkv_h);
    cudaGetSymbolAddress((void**)&wproj, g_wproj_h);
    cudaGetSymbolAddress((void**)&q,     g_q);
    cudaGetSymbolAddress((void**)&k,     g_k);
    cudaGetSymbolAddress((void**)&v,     g_v);
    cudaGetSymbolAddress((void**)&ao,    g_ao);

    const int gemm_smem = 2 * 3 * 128 * GST * (int)sizeof(__half);     // 61440
    const int attn_smem = (128 + 6 * 64) * AST2 * (int)sizeof(__half); // 73728
    cudaFuncSetAttribute(gemm_h16, cudaFuncAttributeMaxDynamicSharedMemorySize, gemm_smem);
    cudaFuncSetAttribute(attn_h16, cudaFuncAttributeMaxDynamicSharedMemorySize, attn_smem);

    // 0) fp16 preconversion of x and weights
    {
        int n4x = (B_ * N_ * C_) / 4;
        f2h_kernel<<<(n4x + 255) / 256, 256>>>(x, xh, n4x);
        int n4w = (3 * C_ * C_) / 4;
        f2h_kernel<<<(n4w + 255) / 256, 256>>>(qkv_w, wqkv, n4w);
        int n4p = (C_ * C_) / 4;
        f2h_kernel<<<(n4p + 255) / 256, 256>>>(proj_w, wproj, n4p);
    }
    // 1) QKV projection
    {
        dim3 grid(3 * C_ / 128, (B_ * N_) / 128);
        gemm_h16<<<grid, 256, gemm_smem>>>(xh, wqkv, qkv_b, qkv, B_ * N_, 3 * C_, C_);
    }
    // 2) per-head LN + split -> fp16
    {
        int warps = B_ * H_ * N_;
        ln_split<<<warps / 8, 256>>>(qkv, qnw, qnb, knw, knb, q, k, v);
    }
    // 3) attention
    {
        dim3 grid(N_ / 128, BH_);
        attn_h16<<<grid, 256, attn_smem>>>(q, k, v, ao);
    }
    // 4) output projection -> d_out
    {
        dim3 grid(C_ / 128, (B_ * N_) / 128);
        gemm_h16<<<grid, 256, gemm_smem>>>(ao, wproj, proj_b, out, B_ * N_, C_, C_);
    }
}

// round 8
// speedup vs baseline: 7.6468x; 1.1235x over previous
#include <cuda_runtime.h>
#include <cuda_fp16.h>
#include <math.h>
#include <stdint.h>
#include <stddef.h>

#define B_  2
#define N_  4096
#define C_  1024
#define H_  16
#define D_  64
#define BH_ (B_*H_)

// ---------------- scratch (device globals; no allocs allowed) ----------------
__device__ float  g_qkv   [(size_t)B_*N_*3*C_];   // [B,N,3C] fp32
__device__ __half g_xh    [(size_t)B_*N_*C_];     // x in fp16
__device__ __half g_wqkv_h[(size_t)3*C_*C_];      // qkv_w fp16
__device__ __half g_wproj_h[(size_t)C_*C_];       // proj_w fp16
__device__ __half g_q [(size_t)BH_*N_*D_];        // [B,H,N,D] LN'd, pre-scaled by 0.125*log2(e)
__device__ __half g_k [(size_t)BH_*N_*D_];
__device__ __half g_v [(size_t)BH_*N_*D_];
__device__ __half g_ao[(size_t)B_*N_*C_];         // [B,N,C] attention out fp16

// ---------------- helpers ----------------
__device__ __forceinline__ uint32_t packh2(float x, float y) {
    __half2 h = __floats2half2_rn(x, y);
    return *(uint32_t*)&h;
}
__device__ __forceinline__ uint32_t saddr(const void* p) {
    return (uint32_t)__cvta_generic_to_shared(p);
}

__device__ __forceinline__ void mma16(float* c, const uint32_t* a, const uint32_t* b) {
    asm volatile(
        "mma.sync.aligned.m16n8k16.row.col.f32.f16.f16.f32 "
        "{%0,%1,%2,%3}, {%4,%5,%6,%7}, {%8,%9}, {%0,%1,%2,%3};"
        : "+f"(c[0]), "+f"(c[1]), "+f"(c[2]), "+f"(c[3])
        : "r"(a[0]), "r"(a[1]), "r"(a[2]), "r"(a[3]), "r"(b[0]), "r"(b[1]));
}

#define LDSM_X4(R0,R1,R2,R3,ADDR) \
    asm volatile("ldmatrix.sync.aligned.m8n8.x4.shared.b16 {%0,%1,%2,%3}, [%4];" \
        : "=r"(R0), "=r"(R1), "=r"(R2), "=r"(R3) : "r"(ADDR))
#define LDSM_X4T(R0,R1,R2,R3,ADDR) \
    asm volatile("ldmatrix.sync.aligned.m8n8.x4.trans.shared.b16 {%0,%1,%2,%3}, [%4];" \
        : "=r"(R0), "=r"(R1), "=r"(R2), "=r"(R3) : "r"(ADDR))

#define CP_ASYNC16(dst_u32, src) \
    asm volatile("cp.async.cg.shared.global [%0], [%1], 16;" :: "r"(dst_u32), "l"(src))
#define CP_COMMIT() asm volatile("cp.async.commit_group;")
#define CP_WAIT(n)  asm volatile("cp.async.wait_group %0;" :: "n"(n))

// =============================================================================
// fp32 -> fp16 elementwise convert
// =============================================================================
__global__ __launch_bounds__(256) void f2h_kernel(const float* __restrict__ in,
                                                  __half* __restrict__ out, int n4)
{
    int i = blockIdx.x * blockDim.x + threadIdx.x;
    if (i >= n4) return;
    float4 v = ((const float4*)in)[i];
    ((uint2*)out)[i] = make_uint2(packh2(v.x, v.y), packh2(v.z, v.w));
}

// =============================================================================
// fp16 GEMM (proven R6): 128x128, BK=32, 3-stage cp.async, ldmatrix frags
// =============================================================================
#define GST 40

__global__ __launch_bounds__(256, 2) void gemm_h16(
    const __half* __restrict__ A, const __half* __restrict__ W,
    const float* __restrict__ bias, float* __restrict__ Cmat,
    int M, int Nout, int K)
{
    extern __shared__ __half sg[];
    __half* As = sg;
    __half* Bs = sg + 3 * 128 * GST;

    const int tid  = threadIdx.x;
    const int warp = tid >> 5, lane = tid & 31;
    const int mw   = warp >> 2, nw = warp & 3;
    const int g    = lane >> 2, tg = lane & 3;
    const int bm   = blockIdx.y * 128, bn = blockIdx.x * 128;

    const int aR = (lane & 7) + ((lane >> 3) & 1) * 8;
    const int aC = (lane >> 4) * 8;
    const int bR = (lane & 7) + (lane >> 4) * 8;
    const int bC = ((lane >> 3) & 1) * 8;

    const int lrow = tid >> 2;
    const int lc8  = (tid & 3) * 8;

    const __half* Ap = A + (size_t)(bm + lrow) * K + lc8;
    const __half* Wp = W + (size_t)(bn + lrow) * K + lc8;

    const int T = K / 32;

    auto issue = [&](int it) {
        const int st = it % 3;
        __half* as = As + st * 128 * GST;
        __half* bs = Bs + st * 128 * GST;
        CP_ASYNC16(saddr(&as[lrow * GST + lc8]),        Ap + it * 32);
        CP_ASYNC16(saddr(&as[(lrow + 64) * GST + lc8]), Ap + (size_t)64 * K + it * 32);
        CP_ASYNC16(saddr(&bs[lrow * GST + lc8]),        Wp + it * 32);
        CP_ASYNC16(saddr(&bs[(lrow + 64) * GST + lc8]), Wp + (size_t)64 * K + it * 32);
        CP_COMMIT();
    };

    float acc[4][4][4];
    #pragma unroll
    for (int i = 0; i < 4; i++)
        #pragma unroll
        for (int j = 0; j < 4; j++)
            #pragma unroll
            for (int e = 0; e < 4; e++) acc[i][j][e] = 0.f;

    issue(0);
    issue(1);

    for (int it = 0; it < T; it++) {
        if (it < T - 1) { CP_WAIT(1); } else { CP_WAIT(0); }
        __syncthreads();
        if (it + 2 < T) issue(it + 2);

        const int st = it % 3;
        __half* as = As + st * 128 * GST;
        __half* bs = Bs + st * 128 * GST;

        #pragma unroll
        for (int ks = 0; ks < 2; ks++) {
            const int kk = ks * 16;
            uint32_t a[4][4], b[4][2];
            #pragma unroll
            for (int mt = 0; mt < 4; mt++)
                LDSM_X4(a[mt][0], a[mt][1], a[mt][2], a[mt][3],
                        saddr(&as[(mw * 64 + mt * 16 + aR) * GST + kk + aC]));
            #pragma unroll
            for (int np = 0; np < 2; np++) {
                uint32_t r0, r1, r2, r3;
                LDSM_X4(r0, r1, r2, r3,
                        saddr(&bs[(nw * 32 + np * 16 + bR) * GST + kk + bC]));
                b[2*np][0] = r0; b[2*np][1] = r1;
                b[2*np+1][0] = r2; b[2*np+1][1] = r3;
            }
            #pragma unroll
            for (int mt = 0; mt < 4; mt++)
                #pragma unroll
                for (int nt = 0; nt < 4; nt++)
                    mma16(acc[mt][nt], a[mt], b[nt]);
        }
    }

    #pragma unroll
    for (int mt = 0; mt < 4; mt++) {
        const int row0 = bm + mw * 64 + mt * 16 + g;
        #pragma unroll
        for (int nt = 0; nt < 4; nt++) {
            const int col = bn + nw * 32 + nt * 8 + 2 * tg;
            const float b0 = bias[col], b1 = bias[col + 1];
            *(float2*)(Cmat + (size_t)row0 * Nout + col) =
                make_float2(acc[mt][nt][0] + b0, acc[mt][nt][1] + b1);
            *(float2*)(Cmat + (size_t)(row0 + 8) * Nout + col) =
                make_float2(acc[mt][nt][2] + b0, acc[mt][nt][3] + b1);
        }
    }
}

// =============================================================================
// LayerNorm over D=64 per (b,h,n) for q,k + v copy; fp16 outputs.
// q pre-scaled by D^-0.5 * log2(e) so attention can use exp2f directly.
// =============================================================================
__global__ __launch_bounds__(256) void ln_split(
    const float* __restrict__ qkv,
    const float* __restrict__ qw, const float* __restrict__ qb,
    const float* __restrict__ kw, const float* __restrict__ kb,
    __half* __restrict__ Qo, __half* __restrict__ Ko, __half* __restrict__ Vo)
{
    const int gw   = (blockIdx.x * blockDim.x + threadIdx.x) >> 5;
    const int lane = threadIdx.x & 31;
    const int n = gw & (N_ - 1);
    const int h = (gw >> 12) & (H_ - 1);
    const int b = gw >> 16;

    const float* base = qkv + ((size_t)(b * N_ + n)) * (3 * C_) + h * D_;
    const size_t oidx = ((size_t)((b * H_ + h) * N_) + n) * D_ + lane * 2;
    const int d = lane * 2;

    float2 vv = *(const float2*)(base + 2 * C_ + d);
    *(__half2*)(Vo + oidx) = __floats2half2_rn(vv.x, vv.y);

    const float inv64 = 1.f / 64.f;
    {
        float2 qv = *(const float2*)(base + d);
        float s = qv.x + qv.y, ss = qv.x*qv.x + qv.y*qv.y;
        #pragma unroll
        for (int m = 16; m; m >>= 1) {
            s  += __shfl_xor_sync(0xffffffffu, s,  m);
            ss += __shfl_xor_sync(0xffffffffu, ss, m);
        }
        float mu = s * inv64;
        float var = fmaxf(ss * inv64 - mu * mu, 0.f);
        float rstd = rsqrtf(var + 1e-5f);
        const float sc = 0.125f * 1.44269504f;   // D^-0.5 * log2(e)
        float rx = ((qv.x - mu) * rstd * qw[d]     + qb[d])     * sc;
        float ry = ((qv.y - mu) * rstd * qw[d + 1] + qb[d + 1]) * sc;
        *(__half2*)(Qo + oidx) = __floats2half2_rn(rx, ry);
    }
    {
        float2 kv = *(const float2*)(base + C_ + d);
        float s = kv.x + kv.y, ss = kv.x*kv.x + kv.y*kv.y;
        #pragma unroll
        for (int m = 16; m; m >>= 1) {
            s  += __shfl_xor_sync(0xffffffffu, s,  m);
            ss += __shfl_xor_sync(0xffffffffu, ss, m);
        }
        float mu = s * inv64;
        float var = fmaxf(ss * inv64 - mu * mu, 0.f);
        float rstd = rsqrtf(var + 1e-5f);
        float rx = (kv.x - mu) * rstd * kw[d]     + kb[d];
        float ry = (kv.y - mu) * rstd * kw[d + 1] + kb[d + 1];
        *(__half2*)(Ko + oidx) = __floats2half2_rn(rx, ry);
    }
}

// =============================================================================
// Flash attention, fp16 MMA, NO-MAX softmax.
// LN'd q/k have exact row-norm 8 -> |s| <= 8 (natural) -> exp(s) <= e^8, safe.
// q pre-scaled by log2(e): p = exp2f(s). O accumulates with no rescaling;
// l reduced once in the epilogue.
// =============================================================================
#define AST2 72

__global__ __launch_bounds__(256, 2) void attn_h16(
    const __half* __restrict__ Q, const __half* __restrict__ Kg,
    const __half* __restrict__ Vg, __half* __restrict__ AO)
{
    extern __shared__ __half sh[];
    __half* Qs = sh;                      // [128][AST2]
    __half* Ks = Qs + 128 * AST2;         // [3][64][AST2]
    __half* Vs = Ks + 3 * 64 * AST2;      // [3][64][AST2]

    const int tid  = threadIdx.x;
    const int warp = tid >> 5, lane = tid & 31;
    const int g    = lane >> 2, tg = lane & 3;
    const int bh   = blockIdx.y;
    const int q0   = blockIdx.x * 128;
    const int mrow = warp * 16;

    const int aR = (lane & 7) + ((lane >> 3) & 1) * 8;
    const int aC = (lane >> 4) * 8;
    const int bR = (lane & 7) + (lane >> 4) * 8;
    const int bC = ((lane >> 3) & 1) * 8;

    const __half* Qb = Q  + ((size_t)bh * N_ + q0) * D_;
    const __half* Kb = Kg + (size_t)bh * N_ * D_;
    const __half* Vb = Vg + (size_t)bh * N_ * D_;

    // ---- load Q tile (128x64 halves) ----
    #pragma unroll
    for (int j = 0; j < 4; j++) {
        const int id  = tid + 256 * j;
        const int row = id >> 3;
        const int c8  = (id & 7) * 8;
        *(uint4*)&Qs[row * AST2 + c8] = *(const uint4*)(Qb + (size_t)row * D_ + c8);
    }

    const int lrow = tid >> 2;
    const int lc8  = (tid & 3) * 8;

    auto issueKV = [&](int t) {
        const int st = t % 3;
        const __half* kp = Kb + (size_t)(t * 64 + lrow) * D_ + lc8;
        const __half* vp = Vb + (size_t)(t * 64 + lrow) * D_ + lc8;
        __half* ks = &Ks[(st * 64 + lrow) * AST2 + lc8];
        __half* vs = &Vs[(st * 64 + lrow) * AST2 + lc8];
        CP_ASYNC16(saddr(ks),      kp);
        CP_ASYNC16(saddr(ks + 32), kp + 32);
        CP_ASYNC16(saddr(vs),      vp);
        CP_ASYNC16(saddr(vs + 32), vp + 32);
        CP_COMMIT();
    };

    issueKV(0);
    issueKV(1);
    __syncthreads();   // Q stores visible

    // ---- Q fragments, register resident ----
    uint32_t qf[4][4];
    #pragma unroll
    for (int ks = 0; ks < 4; ks++)
        LDSM_X4(qf[ks][0], qf[ks][1], qf[ks][2], qf[ks][3],
                saddr(&Qs[(mrow + aR) * AST2 + ks * 16 + aC]));

    float o[8][4];
    #pragma unroll
    for (int nt = 0; nt < 8; nt++)
        #pragma unroll
        for (int e = 0; e < 4; e++) o[nt][e] = 0.f;
    float ls[2] = { 0.f, 0.f };   // thread-local partial row sums

    const int T = N_ / 64;
    for (int t = 0; t < T; t++) {
        if (t < T - 1) { CP_WAIT(1); } else { CP_WAIT(0); }
        __syncthreads();
        if (t + 2 < T) issueKV(t + 2);

        const int st = t % 3;
        const __half* Kc = Ks + st * 64 * AST2;
        const __half* Vc = Vs + st * 64 * AST2;

        // ---- S = Q @ K^T (warp: 16x64) ----
        float sacc[8][4];
        #pragma unroll
        for (int nt = 0; nt < 8; nt++)
            #pragma unroll
            for (int e = 0; e < 4; e++) sacc[nt][e] = 0.f;

        #pragma unroll
        for (int ks = 0; ks < 4; ks++) {
            const int kk = ks * 16;
            #pragma unroll
            for (int np = 0; np < 4; np++) {
                uint32_t r0, r1, r2, r3;
                LDSM_X4(r0, r1, r2, r3,
                        saddr(&Kc[(np * 16 + bR) * AST2 + kk + bC]));
                uint32_t b0[2] = { r0, r1 }, b1[2] = { r2, r3 };
                mma16(sacc[2*np],     qf[ks], b0);
                mma16(sacc[2*np + 1], qf[ks], b1);
            }
        }

        // ---- no-max softmax: p = exp2(s) (s already in log2 units) ----
        #pragma unroll
        for (int nt = 0; nt < 8; nt++) {
            #pragma unroll
            for (int e = 0; e < 4; e++) {
                float p = exp2f(sacc[nt][e]);
                sacc[nt][e] = p;
                ls[e >> 1] += p;
            }
        }

        // ---- O += P @ V : P from regs, V^T via ldmatrix.trans ----
        #pragma unroll
        for (int ks = 0; ks < 4; ks++) {
            const int kk = ks * 16;
            uint32_t a[4];
            a[0] = packh2(sacc[2*ks    ][0], sacc[2*ks    ][1]);
            a[1] = packh2(sacc[2*ks    ][2], sacc[2*ks    ][3]);
            a[2] = packh2(sacc[2*ks + 1][0], sacc[2*ks + 1][1]);
            a[3] = packh2(sacc[2*ks + 1][2], sacc[2*ks + 1][3]);
            #pragma unroll
            for (int dp = 0; dp < 4; dp++) {
                uint32_t r0, r1, r2, r3;
                LDSM_X4T(r0, r1, r2, r3,
                         saddr(&Vc[(kk + aR) * AST2 + dp * 16 + aC]));
                uint32_t b0[2] = { r0, r1 }, b1[2] = { r2, r3 };
                mma16(o[2*dp],     a, b0);
                mma16(o[2*dp + 1], a, b1);
            }
        }
    }

    // ---- epilogue: single l-reduction across the 4 tg lanes, normalize ----
    #pragma unroll
    for (int hh = 0; hh < 2; hh++) {
        ls[hh] += __shfl_xor_sync(0xffffffffu, ls[hh], 1);
        ls[hh] += __shfl_xor_sync(0xffffffffu, ls[hh], 2);
    }
    const float inv0 = 1.f / ls[0], inv1 = 1.f / ls[1];

    const int b = bh >> 4, h = bh & 15;
    __half* op = AO + ((size_t)(b * N_ + q0 + mrow + g)) * C_ + h * D_;
    #pragma unroll
    for (int nt = 0; nt < 8; nt++) {
        const int col = nt * 8 + 2 * tg;
        *(__half2*)(op + col) = __floats2half2_rn(o[nt][0] * inv0, o[nt][1] * inv0);
        *(__half2*)(op + (size_t)8 * C_ + col) =
            __floats2half2_rn(o[nt][2] * inv1, o[nt][3] * inv1);
    }
}

// =============================================================================
extern "C" void kernel_launch(void* const* d_in, const int* in_sizes, int n_in,
                              void* d_out, int out_size)
{
    const float* x      = (const float*)d_in[0];
    const float* qkv_w  = (const float*)d_in[1];
    const float* qkv_b  = (const float*)d_in[2];
    const float* qnw    = (const float*)d_in[3];
    const float* qnb    = (const float*)d_in[4];
    const float* knw    = (const float*)d_in[5];
    const float* knb    = (const float*)d_in[6];
    const float* proj_w = (const float*)d_in[7];
    const float* proj_b = (const float*)d_in[8];
    float* out = (float*)d_out;

    float *qkv; __half *xh, *wqkv, *wproj, *q, *k, *v, *ao;
    cudaGetSymbolAddress((void**)&qkv,   g_qkv);
    cudaGetSymbolAddress((void**)&xh,    g_xh);
    cudaGetSymbolAddress((void**)&wqkv,  g_wqkv_h);
    cudaGetSymbolAddress((void**)&wproj, g_wproj_h);
    cudaGetSymbolAddress((void**)&q,     g_q);
    cudaGetSymbolAddress((void**)&k,     g_k);
    cudaGetSymbolAddress((void**)&v,     g_v);
    cudaGetSymbolAddress((void**)&ao,    g_ao);

    const int gemm_smem = 2 * 3 * 128 * GST * (int)sizeof(__half);     // 61440
    const int attn_smem = (128 + 6 * 64) * AST2 * (int)sizeof(__half); // 73728
    cudaFuncSetAttribute(gemm_h16, cudaFuncAttributeMaxDynamicSharedMemorySize, gemm_smem);
    cudaFuncSetAttribute(attn_h16, cudaFuncAttributeMaxDynamicSharedMemorySize, attn_smem);

    // 0) fp16 preconversion of x and weights
    {
        int n4x = (B_ * N_ * C_) / 4;
        f2h_kernel<<<(n4x + 255) / 256, 256>>>(x, xh, n4x);
        int n4w = (3 * C_ * C_) / 4;
        f2h_kernel<<<(n4w + 255) / 256, 256>>>(qkv_w, wqkv, n4w);
        int n4p = (C_ * C_) / 4;
        f2h_kernel<<<(n4p + 255) / 256, 256>>>(proj_w, wproj, n4p);
    }
    // 1) QKV projection
    {
        dim3 grid(3 * C_ / 128, (B_ * N_) / 128);
        gemm_h16<<<grid, 256, gemm_smem>>>(xh, wqkv, qkv_b, qkv, B_ * N_, 3 * C_, C_);
    }
    // 2) per-head LN + split -> fp16 (q pre-scaled by D^-0.5*log2e)
    {
        int warps = B_ * H_ * N_;
        ln_split<<<warps / 8, 256>>>(qkv, qnw, qnb, knw, knb, q, k, v);
    }
    // 3) attention (no-max softmax)
    {
        dim3 grid(N_ / 128, BH_);
        attn_h16<<<grid, 256, attn_smem>>>(q, k, v, ao);
    }
    // 4) output projection -> d_out
    {
        dim3 grid(C_ / 128, (B_ * N_) / 128);
        gemm_h16<<<grid, 256, gemm_smem>>>(ao, wproj, proj_b, out, B_ * N_, C_, C_);
    }
}

// round 9
// speedup vs baseline: 8.1410x; 1.0646x over previous
#include <cuda_runtime.h>
#include <cuda_fp16.h>
#include <math.h>
#include <stdint.h>
#include <stddef.h>

#define B_  2
#define N_  4096
#define C_  1024
#define H_  16
#define D_  64
#define BH_ (B_*H_)

// ---------------- scratch (device globals; no allocs allowed) ----------------
__device__ __half g_xh    [(size_t)B_*N_*C_];     // x in fp16
__device__ __half g_wqkv_h[(size_t)3*C_*C_];      // qkv_w fp16
__device__ __half g_wproj_h[(size_t)C_*C_];       // proj_w fp16
__device__ __half g_q [(size_t)BH_*N_*D_];        // LN'd, pre-scaled by 0.125*log2e
__device__ __half g_k [(size_t)BH_*N_*D_];
__device__ __half g_v [(size_t)BH_*N_*D_];
__device__ __half g_ao[(size_t)B_*N_*C_];         // [B,N,C] attention out fp16

// ---------------- helpers ----------------
__device__ __forceinline__ uint32_t packh2(float x, float y) {
    __half2 h = __floats2half2_rn(x, y);
    return *(uint32_t*)&h;
}
__device__ __forceinline__ uint32_t saddr(const void* p) {
    return (uint32_t)__cvta_generic_to_shared(p);
}

__device__ __forceinline__ void mma16(float* c, const uint32_t* a, const uint32_t* b) {
    asm volatile(
        "mma.sync.aligned.m16n8k16.row.col.f32.f16.f16.f32 "
        "{%0,%1,%2,%3}, {%4,%5,%6,%7}, {%8,%9}, {%0,%1,%2,%3};"
        : "+f"(c[0]), "+f"(c[1]), "+f"(c[2]), "+f"(c[3])
        : "r"(a[0]), "r"(a[1]), "r"(a[2]), "r"(a[3]), "r"(b[0]), "r"(b[1]));
}

#define LDSM_X4(R0,R1,R2,R3,ADDR) \
    asm volatile("ldmatrix.sync.aligned.m8n8.x4.shared.b16 {%0,%1,%2,%3}, [%4];" \
        : "=r"(R0), "=r"(R1), "=r"(R2), "=r"(R3) : "r"(ADDR))
#define LDSM_X4T(R0,R1,R2,R3,ADDR) \
    asm volatile("ldmatrix.sync.aligned.m8n8.x4.trans.shared.b16 {%0,%1,%2,%3}, [%4];" \
        : "=r"(R0), "=r"(R1), "=r"(R2), "=r"(R3) : "r"(ADDR))

#define CP_ASYNC16(dst_u32, src) \
    asm volatile("cp.async.cg.shared.global [%0], [%1], 16;" :: "r"(dst_u32), "l"(src))
#define CP_COMMIT() asm volatile("cp.async.commit_group;")
#define CP_WAIT(n)  asm volatile("cp.async.wait_group %0;" :: "n"(n))

// =============================================================================
// fp32 -> fp16 elementwise convert
// =============================================================================
__global__ __launch_bounds__(256) void f2h_kernel(const float* __restrict__ in,
                                                  __half* __restrict__ out, int n4)
{
    int i = blockIdx.x * blockDim.x + threadIdx.x;
    if (i >= n4) return;
    float4 v = ((const float4*)in)[i];
    ((uint2*)out)[i] = make_uint2(packh2(v.x, v.y), packh2(v.z, v.w));
}

#define GST 40

// =============================================================================
// QKV GEMM with fused bias + per-head LayerNorm epilogue.
// 128x128 tile, BK=32, 3-stage cp.async. Warps 4x2, warp tile 32x64 so each
// warp owns one head's full D=64 -> LN reduction = 2 shuffles.
// Writes q (LN'd, *0.125*log2e), k (LN'd), v (bias only) as fp16 [bh][n][d].
// =============================================================================
__global__ __launch_bounds__(256, 2) void gemm_qkv_ln(
    const __half* __restrict__ A, const __half* __restrict__ W,
    const float* __restrict__ bias,
    const float* __restrict__ qw, const float* __restrict__ qb,
    const float* __restrict__ kw, const float* __restrict__ kb,
    __half* __restrict__ Qo, __half* __restrict__ Ko, __half* __restrict__ Vo)
{
    extern __shared__ __half sg[];
    __half* As = sg;
    __half* Bs = sg + 3 * 128 * GST;

    const int K = C_;
    const int tid  = threadIdx.x;
    const int warp = tid >> 5, lane = tid & 31;
    const int mw   = warp >> 1, nw = warp & 1;      // 4 x 2 warp grid
    const int g    = lane >> 2, tg = lane & 3;
    const int bm   = blockIdx.y * 128, bn = blockIdx.x * 128;

    const int aR = (lane & 7) + ((lane >> 3) & 1) * 8;
    const int aC = (lane >> 4) * 8;
    const int bR = (lane & 7) + (lane >> 4) * 8;
    const int bC = ((lane >> 3) & 1) * 8;

    const int lrow = tid >> 2;
    const int lc8  = (tid & 3) * 8;

    const __half* Ap = A + (size_t)(bm + lrow) * K + lc8;
    const __half* Wp = W + (size_t)(bn + lrow) * K + lc8;

    const int T = K / 32;

    auto issue = [&](int it) {
        const int st = it % 3;
        __half* as = As + st * 128 * GST;
        __half* bs = Bs + st * 128 * GST;
        CP_ASYNC16(saddr(&as[lrow * GST + lc8]),        Ap + it * 32);
        CP_ASYNC16(saddr(&as[(lrow + 64) * GST + lc8]), Ap + (size_t)64 * K + it * 32);
        CP_ASYNC16(saddr(&bs[lrow * GST + lc8]),        Wp + it * 32);
        CP_ASYNC16(saddr(&bs[(lrow + 64) * GST + lc8]), Wp + (size_t)64 * K + it * 32);
        CP_COMMIT();
    };

    float acc[2][8][4];
    #pragma unroll
    for (int i = 0; i < 2; i++)
        #pragma unroll
        for (int j = 0; j < 8; j++)
            #pragma unroll
            for (int e = 0; e < 4; e++) acc[i][j][e] = 0.f;

    issue(0);
    issue(1);

    for (int it = 0; it < T; it++) {
        if (it < T - 1) { CP_WAIT(1); } else { CP_WAIT(0); }
        __syncthreads();
        if (it + 2 < T) issue(it + 2);

        const int st = it % 3;
        __half* as = As + st * 128 * GST;
        __half* bs = Bs + st * 128 * GST;

        #pragma unroll
        for (int ks = 0; ks < 2; ks++) {
            const int kk = ks * 16;
            uint32_t a[2][4], b[8][2];
            #pragma unroll
            for (int mt = 0; mt < 2; mt++)
                LDSM_X4(a[mt][0], a[mt][1], a[mt][2], a[mt][3],
                        saddr(&as[(mw * 32 + mt * 16 + aR) * GST + kk + aC]));
            #pragma unroll
            for (int np = 0; np < 4; np++) {
                uint32_t r0, r1, r2, r3;
                LDSM_X4(r0, r1, r2, r3,
                        saddr(&bs[(nw * 64 + np * 16 + bR) * GST + kk + bC]));
                b[2*np][0] = r0; b[2*np][1] = r1;
                b[2*np+1][0] = r2; b[2*np+1][1] = r3;
            }
            #pragma unroll
            for (int mt = 0; mt < 2; mt++)
                #pragma unroll
                for (int nt = 0; nt < 8; nt++)
                    mma16(acc[mt][nt], a[mt], b[nt]);
        }
    }

    // ---- fused epilogue: bias + (LN for q/k) + fp16 write ----
    const int cn0 = bn + nw * 64;          // warp-uniform
    const int sec = cn0 >> 10;             // 0=q, 1=k, 2=v
    const int h   = (cn0 >> 6) & 15;

    float bz[16];
    #pragma unroll
    for (int nt = 0; nt < 8; nt++) {
        bz[2*nt]   = bias[cn0 + nt*8 + 2*tg];
        bz[2*nt+1] = bias[cn0 + nt*8 + 2*tg + 1];
    }
    float lnw[16], lnb[16];
    if (sec < 2) {
        const float* ws = (sec == 0) ? qw : kw;
        const float* bs2 = (sec == 0) ? qb : kb;
        #pragma unroll
        for (int nt = 0; nt < 8; nt++) {
            lnw[2*nt]   = ws[nt*8 + 2*tg];
            lnw[2*nt+1] = ws[nt*8 + 2*tg + 1];
            lnb[2*nt]   = bs2[nt*8 + 2*tg];
            lnb[2*nt+1] = bs2[nt*8 + 2*tg + 1];
        }
    }
    __half* dst = (sec == 0) ? Qo : (sec == 1) ? Ko : Vo;
    const float osc = (sec == 0) ? 0.125f * 1.44269504f : 1.0f;
    const float inv64 = 1.f / 64.f;

    #pragma unroll
    for (int mt = 0; mt < 2; mt++) {
        #pragma unroll
        for (int hh = 0; hh < 2; hh++) {
            const int grow = bm + mw * 32 + mt * 16 + hh * 8 + g;
            float v[16];
            float s = 0.f, ss = 0.f;
            #pragma unroll
            for (int nt = 0; nt < 8; nt++) {
                v[2*nt]   = acc[mt][nt][2*hh]     + bz[2*nt];
                v[2*nt+1] = acc[mt][nt][2*hh + 1] + bz[2*nt+1];
                s  += v[2*nt] + v[2*nt+1];
                ss += v[2*nt]*v[2*nt] + v[2*nt+1]*v[2*nt+1];
            }
            uint32_t outv[8];
            if (sec < 2) {
                s  += __shfl_xor_sync(0xffffffffu, s, 1);
                s  += __shfl_xor_sync(0xffffffffu, s, 2);
                ss += __shfl_xor_sync(0xffffffffu, ss, 1);
                ss += __shfl_xor_sync(0xffffffffu, ss, 2);
                const float mu = s * inv64;
                const float var = fmaxf(ss * inv64 - mu * mu, 0.f);
                const float rstd = rsqrtf(var + 1e-5f);
                #pragma unroll
                for (int nt = 0; nt < 8; nt++) {
                    float o0 = ((v[2*nt]   - mu) * rstd * lnw[2*nt]   + lnb[2*nt])   * osc;
                    float o1 = ((v[2*nt+1] - mu) * rstd * lnw[2*nt+1] + lnb[2*nt+1]) * osc;
                    outv[nt] = packh2(o0, o1);
                }
            } else {
                #pragma unroll
                for (int nt = 0; nt < 8; nt++)
                    outv[nt] = packh2(v[2*nt], v[2*nt+1]);
            }
            const int bb = grow >> 12, n = grow & (N_ - 1);
            __half* op = dst + ((size_t)((bb * H_ + h) * N_) + n) * D_ + 2 * tg;
            #pragma unroll
            for (int nt = 0; nt < 8; nt++)
                *(uint32_t*)(op + nt * 8) = outv[nt];
        }
    }
}

// =============================================================================
// fp16 GEMM (proven R6) for the output projection: 128x128, BK=32, 2x4 warps.
// =============================================================================
__global__ __launch_bounds__(256, 2) void gemm_h16(
    const __half* __restrict__ A, const __half* __restrict__ W,
    const float* __restrict__ bias, float* __restrict__ Cmat,
    int M, int Nout, int K)
{
    extern __shared__ __half sg[];
    __half* As = sg;
    __half* Bs = sg + 3 * 128 * GST;

    const int tid  = threadIdx.x;
    const int warp = tid >> 5, lane = tid & 31;
    const int mw   = warp >> 2, nw = warp & 3;
    const int g    = lane >> 2, tg = lane & 3;
    const int bm   = blockIdx.y * 128, bn = blockIdx.x * 128;

    const int aR = (lane & 7) + ((lane >> 3) & 1) * 8;
    const int aC = (lane >> 4) * 8;
    const int bR = (lane & 7) + (lane >> 4) * 8;
    const int bC = ((lane >> 3) & 1) * 8;

    const int lrow = tid >> 2;
    const int lc8  = (tid & 3) * 8;

    const __half* Ap = A + (size_t)(bm + lrow) * K + lc8;
    const __half* Wp = W + (size_t)(bn + lrow) * K + lc8;

    const int T = K / 32;

    auto issue = [&](int it) {
        const int st = it % 3;
        __half* as = As + st * 128 * GST;
        __half* bs = Bs + st * 128 * GST;
        CP_ASYNC16(saddr(&as[lrow * GST + lc8]),        Ap + it * 32);
        CP_ASYNC16(saddr(&as[(lrow + 64) * GST + lc8]), Ap + (size_t)64 * K + it * 32);
        CP_ASYNC16(saddr(&bs[lrow * GST + lc8]),        Wp + it * 32);
        CP_ASYNC16(saddr(&bs[(lrow + 64) * GST + lc8]), Wp + (size_t)64 * K + it * 32);
        CP_COMMIT();
    };

    float acc[4][4][4];
    #pragma unroll
    for (int i = 0; i < 4; i++)
        #pragma unroll
        for (int j = 0; j < 4; j++)
            #pragma unroll
            for (int e = 0; e < 4; e++) acc[i][j][e] = 0.f;

    issue(0);
    issue(1);

    for (int it = 0; it < T; it++) {
        if (it < T - 1) { CP_WAIT(1); } else { CP_WAIT(0); }
        __syncthreads();
        if (it + 2 < T) issue(it + 2);

        const int st = it % 3;
        __half* as = As + st * 128 * GST;
        __half* bs = Bs + st * 128 * GST;

        #pragma unroll
        for (int ks = 0; ks < 2; ks++) {
            const int kk = ks * 16;
            uint32_t a[4][4], b[4][2];
            #pragma unroll
            for (int mt = 0; mt < 4; mt++)
                LDSM_X4(a[mt][0], a[mt][1], a[mt][2], a[mt][3],
                        saddr(&as[(mw * 64 + mt * 16 + aR) * GST + kk + aC]));
            #pragma unroll
            for (int np = 0; np < 2; np++) {
                uint32_t r0, r1, r2, r3;
                LDSM_X4(r0, r1, r2, r3,
                        saddr(&bs[(nw * 32 + np * 16 + bR) * GST + kk + bC]));
                b[2*np][0] = r0; b[2*np][1] = r1;
                b[2*np+1][0] = r2; b[2*np+1][1] = r3;
            }
            #pragma unroll
            for (int mt = 0; mt < 4; mt++)
                #pragma unroll
                for (int nt = 0; nt < 4; nt++)
                    mma16(acc[mt][nt], a[mt], b[nt]);
        }
    }

    #pragma unroll
    for (int mt = 0; mt < 4; mt++) {
        const int row0 = bm + mw * 64 + mt * 16 + g;
        #pragma unroll
        for (int nt = 0; nt < 4; nt++) {
            const int col = bn + nw * 32 + nt * 8 + 2 * tg;
            const float b0 = bias[col], b1 = bias[col + 1];
            *(float2*)(Cmat + (size_t)row0 * Nout + col) =
                make_float2(acc[mt][nt][0] + b0, acc[mt][nt][1] + b1);
            *(float2*)(Cmat + (size_t)(row0 + 8) * Nout + col) =
                make_float2(acc[mt][nt][2] + b0, acc[mt][nt][3] + b1);
        }
    }
}

// =============================================================================
// Flash attention, fp16 MMA, no-max softmax with ex2.approx.f16x2 and
// row-sum l computed by a ones-MMA (fp32 accumulator, zero shuffles).
// =============================================================================
#define AST2 72

__global__ __launch_bounds__(256, 2) void attn_h16(
    const __half* __restrict__ Q, const __half* __restrict__ Kg,
    const __half* __restrict__ Vg, __half* __restrict__ AO)
{
    extern __shared__ __half sh[];
    __half* Qs = sh;                      // [128][AST2]
    __half* Ks = Qs + 128 * AST2;         // [3][64][AST2]
    __half* Vs = Ks + 3 * 64 * AST2;      // [3][64][AST2]

    const int tid  = threadIdx.x;
    const int warp = tid >> 5, lane = tid & 31;
    const int g    = lane >> 2, tg = lane & 3;
    const int bh   = blockIdx.y;
    const int q0   = blockIdx.x * 128;
    const int mrow = warp * 16;

    const int aR = (lane & 7) + ((lane >> 3) & 1) * 8;
    const int aC = (lane >> 4) * 8;
    const int bR = (lane & 7) + (lane >> 4) * 8;
    const int bC = ((lane >> 3) & 1) * 8;

    const __half* Qb = Q  + ((size_t)bh * N_ + q0) * D_;
    const __half* Kb = Kg + (size_t)bh * N_ * D_;
    const __half* Vb = Vg + (size_t)bh * N_ * D_;

    #pragma unroll
    for (int j = 0; j < 4; j++) {
        const int id  = tid + 256 * j;
        const int row = id >> 3;
        const int c8  = (id & 7) * 8;
        *(uint4*)&Qs[row * AST2 + c8] = *(const uint4*)(Qb + (size_t)row * D_ + c8);
    }

    const int lrow = tid >> 2;
    const int lc8  = (tid & 3) * 8;

    auto issueKV = [&](int t) {
        const int st = t % 3;
        const __half* kp = Kb + (size_t)(t * 64 + lrow) * D_ + lc8;
        const __half* vp = Vb + (size_t)(t * 64 + lrow) * D_ + lc8;
        __half* ks = &Ks[(st * 64 + lrow) * AST2 + lc8];
        __half* vs = &Vs[(st * 64 + lrow) * AST2 + lc8];
        CP_ASYNC16(saddr(ks),      kp);
        CP_ASYNC16(saddr(ks + 32), kp + 32);
        CP_ASYNC16(saddr(vs),      vp);
        CP_ASYNC16(saddr(vs + 32), vp + 32);
        CP_COMMIT();
    };

    issueKV(0);
    issueKV(1);
    __syncthreads();

    uint32_t qf[4][4];
    #pragma unroll
    for (int ks = 0; ks < 4; ks++)
        LDSM_X4(qf[ks][0], qf[ks][1], qf[ks][2], qf[ks][3],
                saddr(&Qs[(mrow + aR) * AST2 + ks * 16 + aC]));

    float o[8][4];
    #pragma unroll
    for (int nt = 0; nt < 8; nt++)
        #pragma unroll
        for (int e = 0; e < 4; e++) o[nt][e] = 0.f;
    float lacc[4] = { 0.f, 0.f, 0.f, 0.f };
    const uint32_t bones[2] = { 0x3C003C00u, 0x3C003C00u };

    const int T = N_ / 64;
    for (int t = 0; t < T; t++) {
        if (t < T - 1) { CP_WAIT(1); } else { CP_WAIT(0); }
        __syncthreads();
        if (t + 2 < T) issueKV(t + 2);

        const int st = t % 3;
        const __half* Kc = Ks + st * 64 * AST2;
        const __half* Vc = Vs + st * 64 * AST2;

        // ---- S = Q @ K^T ----
        float sacc[8][4];
        #pragma unroll
        for (int nt = 0; nt < 8; nt++)
            #pragma unroll
            for (int e = 0; e < 4; e++) sacc[nt][e] = 0.f;

        #pragma unroll
        for (int ks = 0; ks < 4; ks++) {
            const int kk = ks * 16;
            #pragma unroll
            for (int np = 0; np < 4; np++) {
                uint32_t r0, r1, r2, r3;
                LDSM_X4(r0, r1, r2, r3,
                        saddr(&Kc[(np * 16 + bR) * AST2 + kk + bC]));
                uint32_t b0[2] = { r0, r1 }, b1[2] = { r2, r3 };
                mma16(sacc[2*np],     qf[ks], b0);
                mma16(sacc[2*np + 1], qf[ks], b1);
            }
        }

        // ---- p = exp2(s) directly in f16x2 (s pre-scaled by log2e) ----
        uint32_t ph[8][2];
        #pragma unroll
        for (int nt = 0; nt < 8; nt++) {
            uint32_t lo = packh2(sacc[nt][0], sacc[nt][1]);
            uint32_t hi = packh2(sacc[nt][2], sacc[nt][3]);
            asm("ex2.approx.f16x2 %0, %1;" : "=r"(ph[nt][0]) : "r"(lo));
            asm("ex2.approx.f16x2 %0, %1;" : "=r"(ph[nt][1]) : "r"(hi));
        }

        // ---- O += P @ V ; l += P @ ones ----
        #pragma unroll
        for (int ks = 0; ks < 4; ks++) {
            const int kk = ks * 16;
            uint32_t a[4] = { ph[2*ks][0], ph[2*ks][1], ph[2*ks+1][0], ph[2*ks+1][1] };
            mma16(lacc, a, bones);
            #pragma unroll
            for (int dp = 0; dp < 4; dp++) {
                uint32_t r0, r1, r2, r3;
                LDSM_X4T(r0, r1, r2, r3,
                         saddr(&Vc[(kk + aR) * AST2 + dp * 16 + aC]));
                uint32_t b0[2] = { r0, r1 }, b1[2] = { r2, r3 };
                mma16(o[2*dp],     a, b0);
                mma16(o[2*dp + 1], a, b1);
            }
        }
    }

    // ---- epilogue: l already reduced by the ones-MMA ----
    const float inv0 = 1.f / lacc[0], inv1 = 1.f / lacc[2];

    const int b = bh >> 4, h = bh & 15;
    __half* op = AO + ((size_t)(b * N_ + q0 + mrow + g)) * C_ + h * D_;
    #pragma unroll
    for (int nt = 0; nt < 8; nt++) {
        const int col = nt * 8 + 2 * tg;
        *(__half2*)(op + col) = __floats2half2_rn(o[nt][0] * inv0, o[nt][1] * inv0);
        *(__half2*)(op + (size_t)8 * C_ + col) =
            __floats2half2_rn(o[nt][2] * inv1, o[nt][3] * inv1);
    }
}

// =============================================================================
extern "C" void kernel_launch(void* const* d_in, const int* in_sizes, int n_in,
                              void* d_out, int out_size)
{
    const float* x      = (const float*)d_in[0];
    const float* qkv_w  = (const float*)d_in[1];
    const float* qkv_b  = (const float*)d_in[2];
    const float* qnw    = (const float*)d_in[3];
    const float* qnb    = (const float*)d_in[4];
    const float* knw    = (const float*)d_in[5];
    const float* knb    = (const float*)d_in[6];
    const float* proj_w = (const float*)d_in[7];
    const float* proj_b = (const float*)d_in[8];
    float* out = (float*)d_out;

    __half *xh, *wqkv, *wproj, *q, *k, *v, *ao;
    cudaGetSymbolAddress((void**)&xh,    g_xh);
    cudaGetSymbolAddress((void**)&wqkv,  g_wqkv_h);
    cudaGetSymbolAddress((void**)&wproj, g_wproj_h);
    cudaGetSymbolAddress((void**)&q,     g_q);
    cudaGetSymbolAddress((void**)&k,     g_k);
    cudaGetSymbolAddress((void**)&v,     g_v);
    cudaGetSymbolAddress((void**)&ao,    g_ao);

    const int gemm_smem = 2 * 3 * 128 * GST * (int)sizeof(__half);     // 61440
    const int attn_smem = (128 + 6 * 64) * AST2 * (int)sizeof(__half); // 73728
    cudaFuncSetAttribute(gemm_h16, cudaFuncAttributeMaxDynamicSharedMemorySize, gemm_smem);
    cudaFuncSetAttribute(gemm_qkv_ln, cudaFuncAttributeMaxDynamicSharedMemorySize, gemm_smem);
    cudaFuncSetAttribute(attn_h16, cudaFuncAttributeMaxDynamicSharedMemorySize, attn_smem);

    // 0) fp16 preconversion
    {
        int n4x = (B_ * N_ * C_) / 4;
        f2h_kernel<<<(n4x + 255) / 256, 256>>>(x, xh, n4x);
        int n4w = (3 * C_ * C_) / 4;
        f2h_kernel<<<(n4w + 255) / 256, 256>>>(qkv_w, wqkv, n4w);
        int n4p = (C_ * C_) / 4;
        f2h_kernel<<<(n4p + 255) / 256, 256>>>(proj_w, wproj, n4p);
    }
    // 1) QKV projection + fused bias/LN/split -> q,k,v fp16
    {
        dim3 grid(3 * C_ / 128, (B_ * N_) / 128);
        gemm_qkv_ln<<<grid, 256, gemm_smem>>>(xh, wqkv, qkv_b,
                                              qnw, qnb, knw, knb, q, k, v);
    }
    // 2) attention
    {
        dim3 grid(N_ / 128, BH_);
        attn_h16<<<grid, 256, attn_smem>>>(q, k, v, ao);
    }
    // 3) output projection -> d_out
    {
        dim3 grid(C_ / 128, (B_ * N_) / 128);
        gemm_h16<<<grid, 256, gemm_smem>>>(ao, wproj, proj_b, out, B_ * N_, C_, C_);
    }
}